// round 1
// baseline (speedup 1.0000x reference)
#include <cuda_runtime.h>
#include <cuda_bf16.h>
#include <math.h>

// Problem constants (fixed by the dataset)
#define NN 100000
#define EE 3200000
#define FIN 128
#define HH  256
#define GG  64
#define HO  128   // H/2

// ---------------- scratch (static device globals; no allocation) -------------
__device__ __align__(16) float g_h [(size_t)NN * HH];
__device__ __align__(16) float g_p0[(size_t)NN * HH];
__device__ __align__(16) float g_p1[(size_t)NN * HH];
__device__ float g_dinv [NN];
__device__ float g_dinv2[NN];
__device__ int   g_deg  [NN];
__device__ __align__(16) float g_psum[GG * HH];
__device__ int   g_pcnt[GG];

// ---------------- helpers ----------------------------------------------------
__device__ __forceinline__ void red_add_v4(float4* addr, float4 v) {
    asm volatile("red.global.add.v4.f32 [%0], {%1,%2,%3,%4};"
                 :: "l"(addr), "f"(v.x), "f"(v.y), "f"(v.z), "f"(v.w)
                 : "memory");
}

// ---------------- per-pass setup ---------------------------------------------
__global__ void zero_kernel() {
    int i = blockIdx.x * blockDim.x + threadIdx.x;
    if (i < NN)      g_deg[i]  = 0;
    if (i < GG * HH) g_psum[i] = 0.f;
    if (i < GG)      g_pcnt[i] = 0;
}

__global__ void deg_kernel(const int* __restrict__ dst) {
    int e = blockIdx.x * blockDim.x + threadIdx.x;
    if (e < EE) atomicAdd(&g_deg[dst[e]], 1);
}

__global__ void dinv_kernel() {
    int i = blockIdx.x * blockDim.x + threadIdx.x;
    if (i < NN) {
        float d = (float)g_deg[i] + 1.0f;
        g_dinv[i]  = rsqrtf(d);
        g_dinv2[i] = 1.0f / d;
    }
}

// ---------------- GEMM: h = act(A) @ W ; agg_init = h/deg + b -----------------
// A is [M,K] row-major, W is [K,256] row-major.
// aSel: 0 -> use Ain pointer (no relu); 1 -> g_p0 with relu; 2 -> g_p1 with relu
// outSel: 0 -> init into g_p0 ; 1 -> init into g_p1
template <int K>
__global__ void __launch_bounds__(256)
gemm_kernel(const float* __restrict__ Ain, const float* __restrict__ W,
            const float* __restrict__ bias, int aSel, int outSel)
{
    const float* A = Ain;
    bool relu = false;
    if (aSel == 1) { A = g_p0; relu = true; }
    else if (aSel == 2) { A = g_p1; relu = true; }
    float* outI = outSel ? g_p1 : g_p0;

    __shared__ float As[16][64];
    __shared__ float Bs[16][64];

    int tid = threadIdx.x;
    int ty = tid >> 4;          // 0..15 -> 4-row group
    int tx = tid & 15;          // 0..15 -> 4-col group
    int rowBase = blockIdx.x * 64;
    int colBase = blockIdx.y * 64;

    float acc[4][4];
#pragma unroll
    for (int i = 0; i < 4; i++)
#pragma unroll
        for (int j = 0; j < 4; j++) acc[i][j] = 0.f;

    int lm = tid >> 2;          // 0..63 : A row within tile
    int lk = (tid & 3) * 4;     // 0,4,8,12 : k offset (float4)
    int grow = rowBase + lm;

    int bk = tid >> 4;          // 0..15 : B k row
    int bn = (tid & 15) * 4;    // B col offset (float4)

    for (int k0 = 0; k0 < K; k0 += 16) {
        float4 av = make_float4(0.f, 0.f, 0.f, 0.f);
        if (grow < NN) {
            av = *reinterpret_cast<const float4*>(A + (size_t)grow * K + k0 + lk);
            if (relu) {
                av.x = fmaxf(av.x, 0.f); av.y = fmaxf(av.y, 0.f);
                av.z = fmaxf(av.z, 0.f); av.w = fmaxf(av.w, 0.f);
            }
        }
        As[lk + 0][lm] = av.x; As[lk + 1][lm] = av.y;
        As[lk + 2][lm] = av.z; As[lk + 3][lm] = av.w;

        float4 bv = *reinterpret_cast<const float4*>(
            W + (size_t)(k0 + bk) * HH + colBase + bn);
        *reinterpret_cast<float4*>(&Bs[bk][bn]) = bv;

        __syncthreads();
#pragma unroll
        for (int kk = 0; kk < 16; kk++) {
            float a0 = As[kk][ty * 4 + 0], a1 = As[kk][ty * 4 + 1];
            float a2 = As[kk][ty * 4 + 2], a3 = As[kk][ty * 4 + 3];
            float b0 = Bs[kk][tx * 4 + 0], b1 = Bs[kk][tx * 4 + 1];
            float b2 = Bs[kk][tx * 4 + 2], b3 = Bs[kk][tx * 4 + 3];
            acc[0][0] += a0 * b0; acc[0][1] += a0 * b1; acc[0][2] += a0 * b2; acc[0][3] += a0 * b3;
            acc[1][0] += a1 * b0; acc[1][1] += a1 * b1; acc[1][2] += a1 * b2; acc[1][3] += a1 * b3;
            acc[2][0] += a2 * b0; acc[2][1] += a2 * b1; acc[2][2] += a2 * b2; acc[2][3] += a2 * b3;
            acc[3][0] += a3 * b0; acc[3][1] += a3 * b1; acc[3][2] += a3 * b2; acc[3][3] += a3 * b3;
        }
        __syncthreads();
    }

    int col = colBase + tx * 4;
    float4 bias4 = *reinterpret_cast<const float4*>(bias + col);
#pragma unroll
    for (int i = 0; i < 4; i++) {
        int r = rowBase + ty * 4 + i;
        if (r < NN) {
            float d2 = g_dinv2[r];
            float4 v = make_float4(acc[i][0], acc[i][1], acc[i][2], acc[i][3]);
            *reinterpret_cast<float4*>(g_h + (size_t)r * HH + col) = v;
            float4 o = make_float4(fmaf(v.x, d2, bias4.x), fmaf(v.y, d2, bias4.y),
                                   fmaf(v.z, d2, bias4.z), fmaf(v.w, d2, bias4.w));
            *reinterpret_cast<float4*>(outI + (size_t)r * HH + col) = o;
        }
    }
}

// ---------------- edge scatter: agg[dst] += dinv[src]*dinv[dst]*h[src] --------
// One warp per edge: coalesced 1KB gather + coalesced vector reductions.
__global__ void __launch_bounds__(256)
scatter_kernel(const int* __restrict__ src, const int* __restrict__ dst, int aggSel)
{
    float* agg = aggSel ? g_p1 : g_p0;
    int w = (int)((blockIdx.x * (unsigned)blockDim.x + threadIdx.x) >> 5);
    int lane = threadIdx.x & 31;
    if (w >= EE) return;
    int s = __ldg(&src[w]);
    int d = __ldg(&dst[w]);
    float coef = g_dinv[s] * g_dinv[d];
    const float4* hrow = reinterpret_cast<const float4*>(g_h + (size_t)s * HH);
    float4*       arow = reinterpret_cast<float4*>(agg + (size_t)d * HH);
#pragma unroll
    for (int it = 0; it < 2; it++) {
        int j = lane + it * 32;
        float4 v = __ldg(&hrow[j]);
        v.x *= coef; v.y *= coef; v.z *= coef; v.w *= coef;
        red_add_v4(&arow[j], v);
    }
}

// ---------------- global mean pool accumulation (reads g_p0) ------------------
__global__ void __launch_bounds__(256)
pool_kernel(const int* __restrict__ batch)
{
    int w = (int)((blockIdx.x * (unsigned)blockDim.x + threadIdx.x) >> 5);
    int lane = threadIdx.x & 31;
    if (w >= NN) return;
    int g = __ldg(&batch[w]);
    if (lane == 0) atomicAdd(&g_pcnt[g], 1);
    const float4* row = reinterpret_cast<const float4*>(g_p0 + (size_t)w * HH);
    float4* dstp = reinterpret_cast<float4*>(g_psum + g * HH);
    float4 v0 = __ldg(&row[lane]);
    float4 v1 = __ldg(&row[lane + 32]);
    red_add_v4(&dstp[lane], v0);
    red_add_v4(&dstp[lane + 32], v1);
}

// ---------------- z = mean @ lin0_W + lin0_b  -> d_out[pass*G*HO] -------------
__global__ void __launch_bounds__(128)
z_kernel(const float* __restrict__ lin0W, const float* __restrict__ lin0b,
         float* __restrict__ outz)
{
    __shared__ float mean[HH];
    int g = blockIdx.x;
    int t = threadIdx.x;  // 0..127
    float c = fmaxf((float)g_pcnt[g], 1.0f);
    mean[t]       = g_psum[g * HH + t] / c;
    mean[t + 128] = g_psum[g * HH + t + 128] / c;
    __syncthreads();
    float acc = lin0b[t];
#pragma unroll 8
    for (int k = 0; k < HH; k++)
        acc = fmaf(mean[k], __ldg(&lin0W[(size_t)k * HO + t]), acc);
    outz[g * HO + t] = acc;
}

// ---------------- triplet head ------------------------------------------------
__global__ void final_kernel(const float* __restrict__ linW,
                             const float* __restrict__ linb,
                             float* __restrict__ out)
{
    __shared__ int s1, s2;
    int g = threadIdx.x;  // 0..63
    if (g == 0) { s1 = 0; s2 = 0; }
    __syncthreads();

    const float* z0 = out;
    const float* z1 = out + GG * HO;
    const float* z2 = out + 2 * GG * HO;
    const float EPS = 1e-6f;

    float dp = 0.f, dn = 0.f;
    float y1 = linb[0], y2 = linb[0];
#pragma unroll 4
    for (int j = 0; j < HO; j++) {
        float a = z0[g * HO + j];
        float b = z1[g * HO + j];
        float c = z2[g * HO + j];
        float e1 = a - b + EPS; dp = fmaf(e1, e1, dp);
        float e2 = a - c + EPS; dn = fmaf(e2, e2, dn);
        float wa = linW[j], wb = linW[HO + j];
        y1 = fmaf(a, wa, fmaf(b, wb, y1));
        y2 = fmaf(a, wa, fmaf(c, wb, y2));
    }
    dp = sqrtf(dp); dn = sqrtf(dn);
    float sp = 1.0f / (1.0f + expf(-y1));
    float sn = 1.0f / (1.0f + expf(-y2));

    const int base = 3 * GG * HO;                 // 24576
    out[base + 1 + g] = sp;                       // score_p
    out[base + 1 + GG + g] = sn;                  // score_n
    if (dn - dp > 0.f) atomicAdd(&s1, 1);
    if (sp - sn > 0.f) atomicAdd(&s2, 1);
    __syncthreads();
    if (g == 0) {
        out[base] = (float)s1;                    // correct
        out[base + 1 + 2 * GG] = (float)s2;       // correct_score
    }
}

// ---------------- host orchestration ------------------------------------------
extern "C" void kernel_launch(void* const* d_in, const int* in_sizes, int n_in,
                              void* d_out, int out_size)
{
    const float* x[3]     = { (const float*)d_in[0], (const float*)d_in[1], (const float*)d_in[2] };
    const int*   ei[3]    = { (const int*)d_in[3], (const int*)d_in[4], (const int*)d_in[5] };
    const int*   batch[3] = { (const int*)d_in[6], (const int*)d_in[7], (const int*)d_in[8] };
    const float* W0 = (const float*)d_in[9];
    const float* b0 = (const float*)d_in[10];
    const float* W1 = (const float*)d_in[11];
    const float* b1 = (const float*)d_in[12];
    const float* W2 = (const float*)d_in[13];
    const float* b2 = (const float*)d_in[14];
    const float* lin0W = (const float*)d_in[15];
    const float* lin0b = (const float*)d_in[16];
    const float* linW  = (const float*)d_in[17];
    const float* linb  = (const float*)d_in[18];
    float* out = (float*)d_out;

    dim3 gemmGrid((NN + 63) / 64, HH / 64);
    int scatterBlocks = (int)(((long long)EE * 32 + 255) / 256);
    int poolBlocks    = (int)(((long long)NN * 32 + 255) / 256);

    for (int p = 0; p < 3; p++) {
        const int* srcp = ei[p];
        const int* dstp = ei[p] + EE;

        zero_kernel<<<(NN + 255) / 256, 256>>>();
        deg_kernel<<<(EE + 255) / 256, 256>>>(dstp);
        dinv_kernel<<<(NN + 255) / 256, 256>>>();

        // layer 0: A = x (K=128), init into p0, scatter into p0
        gemm_kernel<FIN><<<gemmGrid, 256>>>(x[p], W0, b0, /*aSel=*/0, /*outSel=*/0);
        scatter_kernel<<<scatterBlocks, 256>>>(srcp, dstp, /*aggSel=*/0);

        // layer 1: A = relu(p0) (K=256), init into p1, scatter into p1
        gemm_kernel<HH><<<gemmGrid, 256>>>(nullptr, W1, b1, /*aSel=*/1, /*outSel=*/1);
        scatter_kernel<<<scatterBlocks, 256>>>(srcp, dstp, /*aggSel=*/1);

        // layer 2: A = relu(p1) (K=256), init into p0, scatter into p0
        gemm_kernel<HH><<<gemmGrid, 256>>>(nullptr, W2, b2, /*aSel=*/2, /*outSel=*/0);
        scatter_kernel<<<scatterBlocks, 256>>>(srcp, dstp, /*aggSel=*/0);

        // mean pool + lin0 -> z_p written directly into d_out
        pool_kernel<<<poolBlocks, 256>>>(batch[p]);
        z_kernel<<<GG, 128>>>(lin0W, lin0b, out + (size_t)p * GG * HO);
    }

    final_kernel<<<1, GG>>>(linW, linb, out);
}

// round 2
// speedup vs baseline: 2.0684x; 2.0684x over previous
#include <cuda_runtime.h>
#include <cuda_bf16.h>
#include <math.h>

// Problem constants (fixed by the dataset)
#define NN 100000
#define EE 3200000
#define FIN 128
#define HH  256
#define GG  64
#define HO  128   // H/2

// ---------------- scratch (static device globals; no allocation) -------------
__device__ __align__(16) float g_h [(size_t)NN * HH];
__device__ __align__(16) float g_p0[(size_t)NN * HH];
__device__ __align__(16) float g_p1[(size_t)NN * HH];
__device__ float g_dinv [NN];
__device__ float g_dinv2[NN];
__device__ int   g_deg  [NN];
__device__ __align__(16) float g_psum[GG * HH];
__device__ int   g_pcnt[GG];

// CSR scratch
__device__ int   g_rowptr[NN + 1];
__device__ int   g_off[NN];
__device__ int   g_bsum[128];
__device__ int   g_bsum2[128];
__device__ __align__(8) int2 g_epack[EE];   // (src, coef-as-int)

// ---------------- helpers ----------------------------------------------------
__device__ __forceinline__ void red_add_v4(float4* addr, float4 v) {
    asm volatile("red.global.add.v4.f32 [%0], {%1,%2,%3,%4};"
                 :: "l"(addr), "f"(v.x), "f"(v.y), "f"(v.z), "f"(v.w)
                 : "memory");
}

// ---------------- per-pass setup ---------------------------------------------
__global__ void zero_kernel() {
    int i = blockIdx.x * blockDim.x + threadIdx.x;
    if (i < NN)      { g_deg[i] = 0; g_off[i] = 0; }
    if (i < GG * HH) g_psum[i] = 0.f;
    if (i < GG)      g_pcnt[i] = 0;
}

__global__ void deg_kernel(const int* __restrict__ dst) {
    int e = blockIdx.x * blockDim.x + threadIdx.x;
    if (e < EE) atomicAdd(&g_deg[dst[e]], 1);
}

__global__ void dinv_kernel() {
    int i = blockIdx.x * blockDim.x + threadIdx.x;
    if (i < NN) {
        float d = (float)g_deg[i] + 1.0f;
        g_dinv[i]  = rsqrtf(d);
        g_dinv2[i] = 1.0f / d;
    }
}

// ---------------- exclusive scan of deg -> rowptr ------------------------------
__global__ void scan1_kernel() {
    __shared__ int s[1024];
    int t = threadIdx.x;
    int i = blockIdx.x * 1024 + t;
    int v = (i < NN) ? g_deg[i] : 0;
    int x = v;
    s[t] = x;
    __syncthreads();
#pragma unroll
    for (int off = 1; off < 1024; off <<= 1) {
        int y = (t >= off) ? s[t - off] : 0;
        __syncthreads();
        x += y;
        s[t] = x;
        __syncthreads();
    }
    if (i < NN) g_rowptr[i] = x - v;     // exclusive within block
    if (t == 1023) g_bsum[blockIdx.x] = x;
}

__global__ void scan2_kernel() {
    __shared__ int s[128];
    int t = threadIdx.x;
    const int NB = (NN + 1023) >> 10;
    int v = (t < NB) ? g_bsum[t] : 0;
    int x = v;
    s[t] = x;
    __syncthreads();
#pragma unroll
    for (int off = 1; off < 128; off <<= 1) {
        int y = (t >= off) ? s[t - off] : 0;
        __syncthreads();
        x += y;
        s[t] = x;
        __syncthreads();
    }
    g_bsum2[t] = x - v;                  // exclusive block offsets
}

__global__ void scan3_kernel() {
    int i = blockIdx.x * blockDim.x + threadIdx.x;
    if (i < NN) g_rowptr[i] += g_bsum2[i >> 10];
    if (i == 0) g_rowptr[NN] = EE;
}

// ---------------- CSR build: sort edges by dst, pack (src, coef) ---------------
__global__ void csr_kernel(const int* __restrict__ src, const int* __restrict__ dst) {
    int e = blockIdx.x * blockDim.x + threadIdx.x;
    if (e >= EE) return;
    int s = src[e], d = dst[e];
    float coef = g_dinv[s] * g_dinv[d];
    int pos = g_rowptr[d] + atomicAdd(&g_off[d], 1);
    g_epack[pos] = make_int2(s, __float_as_int(coef));
}

__global__ void pcnt_kernel(const int* __restrict__ batch) {
    int i = blockIdx.x * blockDim.x + threadIdx.x;
    if (i < NN) atomicAdd(&g_pcnt[batch[i]], 1);
}

// ---------------- GEMM: h = act(A) @ W  (writes g_h only) ---------------------
// aSel: 0 -> Ain (no relu); 1 -> g_p0 relu; 2 -> g_p1 relu
template <int K>
__global__ void __launch_bounds__(256)
gemm_kernel(const float* __restrict__ Ain, const float* __restrict__ W, int aSel)
{
    const float* A = Ain;
    bool relu = false;
    if (aSel == 1) { A = g_p0; relu = true; }
    else if (aSel == 2) { A = g_p1; relu = true; }

    __shared__ float As[16][64];
    __shared__ float Bs[16][64];

    int tid = threadIdx.x;
    int ty = tid >> 4;
    int tx = tid & 15;
    int rowBase = blockIdx.x * 64;
    int colBase = blockIdx.y * 64;

    float acc[4][4];
#pragma unroll
    for (int i = 0; i < 4; i++)
#pragma unroll
        for (int j = 0; j < 4; j++) acc[i][j] = 0.f;

    int lm = tid >> 2;
    int lk = (tid & 3) * 4;
    int grow = rowBase + lm;
    int bk = tid >> 4;
    int bn = (tid & 15) * 4;

    for (int k0 = 0; k0 < K; k0 += 16) {
        float4 av = make_float4(0.f, 0.f, 0.f, 0.f);
        if (grow < NN) {
            av = *reinterpret_cast<const float4*>(A + (size_t)grow * K + k0 + lk);
            if (relu) {
                av.x = fmaxf(av.x, 0.f); av.y = fmaxf(av.y, 0.f);
                av.z = fmaxf(av.z, 0.f); av.w = fmaxf(av.w, 0.f);
            }
        }
        As[lk + 0][lm] = av.x; As[lk + 1][lm] = av.y;
        As[lk + 2][lm] = av.z; As[lk + 3][lm] = av.w;

        float4 bv = *reinterpret_cast<const float4*>(
            W + (size_t)(k0 + bk) * HH + colBase + bn);
        *reinterpret_cast<float4*>(&Bs[bk][bn]) = bv;

        __syncthreads();
#pragma unroll
        for (int kk = 0; kk < 16; kk++) {
            float a0 = As[kk][ty * 4 + 0], a1 = As[kk][ty * 4 + 1];
            float a2 = As[kk][ty * 4 + 2], a3 = As[kk][ty * 4 + 3];
            float b0 = Bs[kk][tx * 4 + 0], b1 = Bs[kk][tx * 4 + 1];
            float b2 = Bs[kk][tx * 4 + 2], b3 = Bs[kk][tx * 4 + 3];
            acc[0][0] += a0 * b0; acc[0][1] += a0 * b1; acc[0][2] += a0 * b2; acc[0][3] += a0 * b3;
            acc[1][0] += a1 * b0; acc[1][1] += a1 * b1; acc[1][2] += a1 * b2; acc[1][3] += a1 * b3;
            acc[2][0] += a2 * b0; acc[2][1] += a2 * b1; acc[2][2] += a2 * b2; acc[2][3] += a2 * b3;
            acc[3][0] += a3 * b0; acc[3][1] += a3 * b1; acc[3][2] += a3 * b2; acc[3][3] += a3 * b3;
        }
        __syncthreads();
    }

    int col = colBase + tx * 4;
#pragma unroll
    for (int i = 0; i < 4; i++) {
        int r = rowBase + ty * 4 + i;
        if (r < NN) {
            float4 v = make_float4(acc[i][0], acc[i][1], acc[i][2], acc[i][3]);
            *reinterpret_cast<float4*>(g_h + (size_t)r * HH + col) = v;
        }
    }
}

// ---------------- pull aggregation: out[n] = b + h[n]/deg + sum coef*h[src] ---
// One warp per node, 128 columns per launch (colOff = 0 or 128).
__global__ void __launch_bounds__(256)
pull_kernel(const float* __restrict__ bias, int outSel, int colOff,
            const int* __restrict__ batch, int doPool)
{
    float* out = outSel ? g_p1 : g_p0;
    int n = (int)((blockIdx.x * (unsigned)blockDim.x + threadIdx.x) >> 5);
    int lane = threadIdx.x & 31;
    if (n >= NN) return;
    int c = colOff + lane * 4;

    float d2 = g_dinv2[n];
    float4 b4 = *reinterpret_cast<const float4*>(bias + c);
    float4 hv = *reinterpret_cast<const float4*>(g_h + (size_t)n * HH + c);
    float4 acc;
    acc.x = fmaf(hv.x, d2, b4.x);
    acc.y = fmaf(hv.y, d2, b4.y);
    acc.z = fmaf(hv.z, d2, b4.z);
    acc.w = fmaf(hv.w, d2, b4.w);

    int beg = g_rowptr[n];
    int end = g_rowptr[n + 1];
    int e = beg;

    for (; e + 3 < end; e += 4) {
        int2 p0 = g_epack[e + 0];
        int2 p1 = g_epack[e + 1];
        int2 p2 = g_epack[e + 2];
        int2 p3 = g_epack[e + 3];
        float4 v0 = *reinterpret_cast<const float4*>(g_h + (size_t)p0.x * HH + c);
        float4 v1 = *reinterpret_cast<const float4*>(g_h + (size_t)p1.x * HH + c);
        float4 v2 = *reinterpret_cast<const float4*>(g_h + (size_t)p2.x * HH + c);
        float4 v3 = *reinterpret_cast<const float4*>(g_h + (size_t)p3.x * HH + c);
        float c0 = __int_as_float(p0.y), c1 = __int_as_float(p1.y);
        float c2 = __int_as_float(p2.y), c3 = __int_as_float(p3.y);
        acc.x = fmaf(c0, v0.x, acc.x); acc.y = fmaf(c0, v0.y, acc.y);
        acc.z = fmaf(c0, v0.z, acc.z); acc.w = fmaf(c0, v0.w, acc.w);
        acc.x = fmaf(c1, v1.x, acc.x); acc.y = fmaf(c1, v1.y, acc.y);
        acc.z = fmaf(c1, v1.z, acc.z); acc.w = fmaf(c1, v1.w, acc.w);
        acc.x = fmaf(c2, v2.x, acc.x); acc.y = fmaf(c2, v2.y, acc.y);
        acc.z = fmaf(c2, v2.z, acc.z); acc.w = fmaf(c2, v2.w, acc.w);
        acc.x = fmaf(c3, v3.x, acc.x); acc.y = fmaf(c3, v3.y, acc.y);
        acc.z = fmaf(c3, v3.z, acc.z); acc.w = fmaf(c3, v3.w, acc.w);
    }
    for (; e < end; e++) {
        int2 p = g_epack[e];
        float4 v = *reinterpret_cast<const float4*>(g_h + (size_t)p.x * HH + c);
        float cf = __int_as_float(p.y);
        acc.x = fmaf(cf, v.x, acc.x); acc.y = fmaf(cf, v.y, acc.y);
        acc.z = fmaf(cf, v.z, acc.z); acc.w = fmaf(cf, v.w, acc.w);
    }

    *reinterpret_cast<float4*>(out + (size_t)n * HH + c) = acc;

    if (doPool) {
        int g = __ldg(&batch[n]);
        red_add_v4(reinterpret_cast<float4*>(g_psum + g * HH + c), acc);
    }
}

// ---------------- z = mean @ lin0_W + lin0_b  -> d_out[pass*G*HO] -------------
__global__ void __launch_bounds__(128)
z_kernel(const float* __restrict__ lin0W, const float* __restrict__ lin0b,
         float* __restrict__ outz)
{
    __shared__ float mean[HH];
    int g = blockIdx.x;
    int t = threadIdx.x;  // 0..127
    float c = fmaxf((float)g_pcnt[g], 1.0f);
    mean[t]       = g_psum[g * HH + t] / c;
    mean[t + 128] = g_psum[g * HH + t + 128] / c;
    __syncthreads();
    float acc = lin0b[t];
#pragma unroll 8
    for (int k = 0; k < HH; k++)
        acc = fmaf(mean[k], __ldg(&lin0W[(size_t)k * HO + t]), acc);
    outz[g * HO + t] = acc;
}

// ---------------- triplet head ------------------------------------------------
__global__ void final_kernel(const float* __restrict__ linW,
                             const float* __restrict__ linb,
                             float* __restrict__ out)
{
    __shared__ int s1, s2;
    int g = threadIdx.x;  // 0..63
    if (g == 0) { s1 = 0; s2 = 0; }
    __syncthreads();

    const float* z0 = out;
    const float* z1 = out + GG * HO;
    const float* z2 = out + 2 * GG * HO;
    const float EPS = 1e-6f;

    float dp = 0.f, dn = 0.f;
    float y1 = linb[0], y2 = linb[0];
#pragma unroll 4
    for (int j = 0; j < HO; j++) {
        float a = z0[g * HO + j];
        float b = z1[g * HO + j];
        float c = z2[g * HO + j];
        float e1 = a - b + EPS; dp = fmaf(e1, e1, dp);
        float e2 = a - c + EPS; dn = fmaf(e2, e2, dn);
        float wa = linW[j], wb = linW[HO + j];
        y1 = fmaf(a, wa, fmaf(b, wb, y1));
        y2 = fmaf(a, wa, fmaf(c, wb, y2));
    }
    dp = sqrtf(dp); dn = sqrtf(dn);
    float sp = 1.0f / (1.0f + expf(-y1));
    float sn = 1.0f / (1.0f + expf(-y2));

    const int base = 3 * GG * HO;                 // 24576
    out[base + 1 + g] = sp;                       // score_p
    out[base + 1 + GG + g] = sn;                  // score_n
    if (dn - dp > 0.f) atomicAdd(&s1, 1);
    if (sp - sn > 0.f) atomicAdd(&s2, 1);
    __syncthreads();
    if (g == 0) {
        out[base] = (float)s1;                    // correct
        out[base + 1 + 2 * GG] = (float)s2;       // correct_score
    }
}

// ---------------- host orchestration ------------------------------------------
extern "C" void kernel_launch(void* const* d_in, const int* in_sizes, int n_in,
                              void* d_out, int out_size)
{
    const float* x[3]     = { (const float*)d_in[0], (const float*)d_in[1], (const float*)d_in[2] };
    const int*   ei[3]    = { (const int*)d_in[3], (const int*)d_in[4], (const int*)d_in[5] };
    const int*   batch[3] = { (const int*)d_in[6], (const int*)d_in[7], (const int*)d_in[8] };
    const float* W0 = (const float*)d_in[9];
    const float* b0 = (const float*)d_in[10];
    const float* W1 = (const float*)d_in[11];
    const float* b1 = (const float*)d_in[12];
    const float* W2 = (const float*)d_in[13];
    const float* b2 = (const float*)d_in[14];
    const float* lin0W = (const float*)d_in[15];
    const float* lin0b = (const float*)d_in[16];
    const float* linW  = (const float*)d_in[17];
    const float* linb  = (const float*)d_in[18];
    float* out = (float*)d_out;

    dim3 gemmGrid((NN + 63) / 64, HH / 64);
    int pullBlocks = (int)(((long long)NN * 32 + 255) / 256);
    const int NB = (NN + 1023) / 1024;

    for (int p = 0; p < 3; p++) {
        const int* srcp = ei[p];
        const int* dstp = ei[p] + EE;

        // ---- per-pass graph prep ----
        zero_kernel<<<(NN + 255) / 256, 256>>>();
        deg_kernel<<<(EE + 255) / 256, 256>>>(dstp);
        dinv_kernel<<<(NN + 255) / 256, 256>>>();
        scan1_kernel<<<NB, 1024>>>();
        scan2_kernel<<<1, 128>>>();
        scan3_kernel<<<(NN + 255) / 256, 256>>>();
        csr_kernel<<<(EE + 255) / 256, 256>>>(srcp, dstp);
        pcnt_kernel<<<(NN + 255) / 256, 256>>>(batch[p]);

        // ---- layer 0: A = x (K=128) -> h ; pull -> p0
        gemm_kernel<FIN><<<gemmGrid, 256>>>(x[p], W0, 0);
        pull_kernel<<<pullBlocks, 256>>>(b0, /*outSel=*/0, 0,   nullptr, 0);
        pull_kernel<<<pullBlocks, 256>>>(b0, /*outSel=*/0, 128, nullptr, 0);

        // ---- layer 1: A = relu(p0) (K=256) -> h ; pull -> p1
        gemm_kernel<HH><<<gemmGrid, 256>>>(nullptr, W1, 1);
        pull_kernel<<<pullBlocks, 256>>>(b1, /*outSel=*/1, 0,   nullptr, 0);
        pull_kernel<<<pullBlocks, 256>>>(b1, /*outSel=*/1, 128, nullptr, 0);

        // ---- layer 2: A = relu(p1) (K=256) -> h ; pull -> p0, fused pooling
        gemm_kernel<HH><<<gemmGrid, 256>>>(nullptr, W2, 2);
        pull_kernel<<<pullBlocks, 256>>>(b2, /*outSel=*/0, 0,   batch[p], 1);
        pull_kernel<<<pullBlocks, 256>>>(b2, /*outSel=*/0, 128, batch[p], 1);

        // ---- z_p = mean @ lin0_W + lin0_b
        z_kernel<<<GG, 128>>>(lin0W, lin0b, out + (size_t)p * GG * HO);
    }

    final_kernel<<<1, GG>>>(linW, linb, out);
}

// round 3
// speedup vs baseline: 2.5519x; 1.2338x over previous
#include <cuda_runtime.h>
#include <cuda_bf16.h>
#include <math.h>

// Problem constants (fixed by the dataset)
#define NN 100000
#define EE 3200000
#define FIN 128
#define HH  256
#define GG  64
#define HO  128   // H/2

typedef unsigned long long u64;

// ---------------- scratch (static device globals; no allocation) -------------
__device__ __align__(16) float g_h [(size_t)NN * HH];
__device__ __align__(16) float g_p0[(size_t)NN * HH];
__device__ __align__(16) float g_p1[(size_t)NN * HH];
__device__ float g_dinv [NN];
__device__ float g_dinv2[NN];
__device__ int   g_deg  [NN];
__device__ __align__(16) float g_psum[GG * HH];
__device__ int   g_pcnt[GG];

// CSR scratch
__device__ int   g_rowptr[NN + 1];
__device__ int   g_off[NN];
__device__ int   g_bsum[128];
__device__ int   g_bsum2[128];
__device__ __align__(8) int2 g_epack[EE];   // (src, coef-as-int)

// ---------------- helpers ----------------------------------------------------
__device__ __forceinline__ void red_add_v4(float4* addr, float4 v) {
    asm volatile("red.global.add.v4.f32 [%0], {%1,%2,%3,%4};"
                 :: "l"(addr), "f"(v.x), "f"(v.y), "f"(v.z), "f"(v.w)
                 : "memory");
}
__device__ __forceinline__ u64 dup2(float a) {
    u64 r; asm("mov.b64 %0, {%1, %1};" : "=l"(r) : "f"(a)); return r;
}
__device__ __forceinline__ void fma2(u64& acc, u64 a, u64 b) {
    asm("fma.rn.f32x2 %0, %1, %2, %0;" : "+l"(acc) : "l"(a), "l"(b));
}
__device__ __forceinline__ float2 unp2(u64 v) {
    float2 f; asm("mov.b64 {%0, %1}, %2;" : "=f"(f.x), "=f"(f.y) : "l"(v)); return f;
}

// ---------------- per-pass setup ---------------------------------------------
__global__ void zero_kernel() {
    int i = blockIdx.x * blockDim.x + threadIdx.x;
    if (i < NN)      { g_deg[i] = 0; g_off[i] = 0; }
    if (i < GG * HH) g_psum[i] = 0.f;
    if (i < GG)      g_pcnt[i] = 0;
}

__global__ void deg_kernel(const int* __restrict__ dst) {
    int e = blockIdx.x * blockDim.x + threadIdx.x;
    if (e < EE) atomicAdd(&g_deg[dst[e]], 1);
}

__global__ void dinv_kernel() {
    int i = blockIdx.x * blockDim.x + threadIdx.x;
    if (i < NN) {
        float d = (float)g_deg[i] + 1.0f;
        g_dinv[i]  = rsqrtf(d);
        g_dinv2[i] = 1.0f / d;
    }
}

// ---------------- exclusive scan of deg -> rowptr ------------------------------
__global__ void scan1_kernel() {
    __shared__ int s[1024];
    int t = threadIdx.x;
    int i = blockIdx.x * 1024 + t;
    int v = (i < NN) ? g_deg[i] : 0;
    int x = v;
    s[t] = x;
    __syncthreads();
#pragma unroll
    for (int off = 1; off < 1024; off <<= 1) {
        int y = (t >= off) ? s[t - off] : 0;
        __syncthreads();
        x += y;
        s[t] = x;
        __syncthreads();
    }
    if (i < NN) g_rowptr[i] = x - v;
    if (t == 1023) g_bsum[blockIdx.x] = x;
}

__global__ void scan2_kernel() {
    __shared__ int s[128];
    int t = threadIdx.x;
    const int NB = (NN + 1023) >> 10;
    int v = (t < NB) ? g_bsum[t] : 0;
    int x = v;
    s[t] = x;
    __syncthreads();
#pragma unroll
    for (int off = 1; off < 128; off <<= 1) {
        int y = (t >= off) ? s[t - off] : 0;
        __syncthreads();
        x += y;
        s[t] = x;
        __syncthreads();
    }
    g_bsum2[t] = x - v;
}

__global__ void scan3_kernel() {
    int i = blockIdx.x * blockDim.x + threadIdx.x;
    if (i < NN) g_rowptr[i] += g_bsum2[i >> 10];
    if (i == 0) g_rowptr[NN] = EE;
}

// ---------------- CSR build: sort edges by dst, pack (src, coef) ---------------
__global__ void csr_kernel(const int* __restrict__ src, const int* __restrict__ dst) {
    int e = blockIdx.x * blockDim.x + threadIdx.x;
    if (e >= EE) return;
    int s = src[e], d = dst[e];
    float coef = g_dinv[s] * g_dinv[d];
    int pos = g_rowptr[d] + atomicAdd(&g_off[d], 1);
    g_epack[pos] = make_int2(s, __float_as_int(coef));
}

__global__ void pcnt_kernel(const int* __restrict__ batch) {
    int i = blockIdx.x * blockDim.x + threadIdx.x;
    if (i < NN) atomicAdd(&g_pcnt[batch[i]], 1);
}

// ---------------- GEMM: h = act(A) @ W  (FFMA2 128x128 tile) ------------------
// 256 threads = 16x16, each computes 8x8 (rows ty*4+i / +64, cols tx*4+j / +64).
template <int K, bool RELU>
__global__ void __launch_bounds__(256, 2)
gemm2_kernel(const float* __restrict__ A, const float* __restrict__ W,
             float* __restrict__ Hout)
{
    __shared__ float As[16][132];   // [k][m], stride 132 (16B-aligned rows)
    __shared__ float Bs[16][128];   // [k][n]

    const int t  = threadIdx.x;
    const int tx = t & 15;
    const int ty = t >> 4;
    const int rowBase = blockIdx.x * 128;
    const int colBase = blockIdx.y * 128;

    const int arow = t >> 2;          // 0..63
    const int akg  = (t & 3) * 4;     // 0,4,8,12
    const int brow = t >> 5;          // 0..7
    const int bcol = (t & 31) * 4;    // 0..124

    const int r0 = rowBase + arow;
    const int r1 = r0 + 64;

    u64 acc[8][4];
#pragma unroll
    for (int i = 0; i < 8; i++)
#pragma unroll
        for (int j = 0; j < 4; j++) acc[i][j] = 0ull;

    float4 pa0, pa1, pb0, pb1;

    // prefetch chunk 0
    {
        pa0 = make_float4(0.f, 0.f, 0.f, 0.f); pa1 = pa0;
        if (r0 < NN) pa0 = *reinterpret_cast<const float4*>(A + (size_t)r0 * K + akg);
        if (r1 < NN) pa1 = *reinterpret_cast<const float4*>(A + (size_t)r1 * K + akg);
        pb0 = *reinterpret_cast<const float4*>(W + (size_t)brow * HH + colBase + bcol);
        pb1 = *reinterpret_cast<const float4*>(W + (size_t)(8 + brow) * HH + colBase + bcol);
    }

    for (int k0 = 0; k0 < K; k0 += 16) {
        float4 a0 = pa0, a1 = pa1, b0 = pb0, b1 = pb1;
        if (RELU) {
            a0.x = fmaxf(a0.x, 0.f); a0.y = fmaxf(a0.y, 0.f);
            a0.z = fmaxf(a0.z, 0.f); a0.w = fmaxf(a0.w, 0.f);
            a1.x = fmaxf(a1.x, 0.f); a1.y = fmaxf(a1.y, 0.f);
            a1.z = fmaxf(a1.z, 0.f); a1.w = fmaxf(a1.w, 0.f);
        }
        As[akg + 0][arow] = a0.x; As[akg + 1][arow] = a0.y;
        As[akg + 2][arow] = a0.z; As[akg + 3][arow] = a0.w;
        As[akg + 0][64 + arow] = a1.x; As[akg + 1][64 + arow] = a1.y;
        As[akg + 2][64 + arow] = a1.z; As[akg + 3][64 + arow] = a1.w;
        *reinterpret_cast<float4*>(&Bs[brow][bcol])     = b0;
        *reinterpret_cast<float4*>(&Bs[brow + 8][bcol]) = b1;
        __syncthreads();

        if (k0 + 16 < K) {
            int kn = k0 + 16;
            pa0 = make_float4(0.f, 0.f, 0.f, 0.f); pa1 = pa0;
            if (r0 < NN) pa0 = *reinterpret_cast<const float4*>(A + (size_t)r0 * K + kn + akg);
            if (r1 < NN) pa1 = *reinterpret_cast<const float4*>(A + (size_t)r1 * K + kn + akg);
            pb0 = *reinterpret_cast<const float4*>(W + (size_t)(kn + brow) * HH + colBase + bcol);
            pb1 = *reinterpret_cast<const float4*>(W + (size_t)(kn + 8 + brow) * HH + colBase + bcol);
        }

#pragma unroll
        for (int kk = 0; kk < 16; kk++) {
            float4 av0 = *reinterpret_cast<const float4*>(&As[kk][ty * 4]);
            float4 av1 = *reinterpret_cast<const float4*>(&As[kk][64 + ty * 4]);
            ulonglong2 bv0 = *reinterpret_cast<const ulonglong2*>(&Bs[kk][tx * 4]);
            ulonglong2 bv1 = *reinterpret_cast<const ulonglong2*>(&Bs[kk][64 + tx * 4]);
            u64 aa;
            aa = dup2(av0.x);
            fma2(acc[0][0], aa, bv0.x); fma2(acc[0][1], aa, bv0.y);
            fma2(acc[0][2], aa, bv1.x); fma2(acc[0][3], aa, bv1.y);
            aa = dup2(av0.y);
            fma2(acc[1][0], aa, bv0.x); fma2(acc[1][1], aa, bv0.y);
            fma2(acc[1][2], aa, bv1.x); fma2(acc[1][3], aa, bv1.y);
            aa = dup2(av0.z);
            fma2(acc[2][0], aa, bv0.x); fma2(acc[2][1], aa, bv0.y);
            fma2(acc[2][2], aa, bv1.x); fma2(acc[2][3], aa, bv1.y);
            aa = dup2(av0.w);
            fma2(acc[3][0], aa, bv0.x); fma2(acc[3][1], aa, bv0.y);
            fma2(acc[3][2], aa, bv1.x); fma2(acc[3][3], aa, bv1.y);
            aa = dup2(av1.x);
            fma2(acc[4][0], aa, bv0.x); fma2(acc[4][1], aa, bv0.y);
            fma2(acc[4][2], aa, bv1.x); fma2(acc[4][3], aa, bv1.y);
            aa = dup2(av1.y);
            fma2(acc[5][0], aa, bv0.x); fma2(acc[5][1], aa, bv0.y);
            fma2(acc[5][2], aa, bv1.x); fma2(acc[5][3], aa, bv1.y);
            aa = dup2(av1.z);
            fma2(acc[6][0], aa, bv0.x); fma2(acc[6][1], aa, bv0.y);
            fma2(acc[6][2], aa, bv1.x); fma2(acc[6][3], aa, bv1.y);
            aa = dup2(av1.w);
            fma2(acc[7][0], aa, bv0.x); fma2(acc[7][1], aa, bv0.y);
            fma2(acc[7][2], aa, bv1.x); fma2(acc[7][3], aa, bv1.y);
        }
        __syncthreads();
    }

#pragma unroll
    for (int i = 0; i < 8; i++) {
        int r = rowBase + ((i < 4) ? (ty * 4 + i) : (64 + ty * 4 + (i - 4)));
        if (r < NN) {
            float2 c0 = unp2(acc[i][0]), c1 = unp2(acc[i][1]);
            float2 c2 = unp2(acc[i][2]), c3 = unp2(acc[i][3]);
            *reinterpret_cast<float4*>(Hout + (size_t)r * HH + colBase + tx * 4)
                = make_float4(c0.x, c0.y, c1.x, c1.y);
            *reinterpret_cast<float4*>(Hout + (size_t)r * HH + colBase + 64 + tx * 4)
                = make_float4(c2.x, c2.y, c3.x, c3.y);
        }
    }
}

// ---------------- pull aggregation: out[n] = b + h[n]/deg + sum coef*h[src] ---
// One warp per node; blockIdx.y selects the 128-column half.
__global__ void __launch_bounds__(256)
pull_kernel(const float* __restrict__ bias, float* __restrict__ out,
            const int* __restrict__ batch, int doPool)
{
    int n = (int)((blockIdx.x * (unsigned)blockDim.x + threadIdx.x) >> 5);
    int lane = threadIdx.x & 31;
    if (n >= NN) return;
    int c = blockIdx.y * 128 + lane * 4;

    float d2 = g_dinv2[n];
    float4 b4 = *reinterpret_cast<const float4*>(bias + c);
    float4 hv = *reinterpret_cast<const float4*>(g_h + (size_t)n * HH + c);
    float4 acc;
    acc.x = fmaf(hv.x, d2, b4.x);
    acc.y = fmaf(hv.y, d2, b4.y);
    acc.z = fmaf(hv.z, d2, b4.z);
    acc.w = fmaf(hv.w, d2, b4.w);

    int beg = g_rowptr[n];
    int end = g_rowptr[n + 1];
    int e = beg;

    for (; e + 3 < end; e += 4) {
        int2 p0 = g_epack[e + 0];
        int2 p1 = g_epack[e + 1];
        int2 p2 = g_epack[e + 2];
        int2 p3 = g_epack[e + 3];
        float4 v0 = *reinterpret_cast<const float4*>(g_h + (size_t)p0.x * HH + c);
        float4 v1 = *reinterpret_cast<const float4*>(g_h + (size_t)p1.x * HH + c);
        float4 v2 = *reinterpret_cast<const float4*>(g_h + (size_t)p2.x * HH + c);
        float4 v3 = *reinterpret_cast<const float4*>(g_h + (size_t)p3.x * HH + c);
        float c0 = __int_as_float(p0.y), c1 = __int_as_float(p1.y);
        float c2 = __int_as_float(p2.y), c3 = __int_as_float(p3.y);
        acc.x = fmaf(c0, v0.x, acc.x); acc.y = fmaf(c0, v0.y, acc.y);
        acc.z = fmaf(c0, v0.z, acc.z); acc.w = fmaf(c0, v0.w, acc.w);
        acc.x = fmaf(c1, v1.x, acc.x); acc.y = fmaf(c1, v1.y, acc.y);
        acc.z = fmaf(c1, v1.z, acc.z); acc.w = fmaf(c1, v1.w, acc.w);
        acc.x = fmaf(c2, v2.x, acc.x); acc.y = fmaf(c2, v2.y, acc.y);
        acc.z = fmaf(c2, v2.z, acc.z); acc.w = fmaf(c2, v2.w, acc.w);
        acc.x = fmaf(c3, v3.x, acc.x); acc.y = fmaf(c3, v3.y, acc.y);
        acc.z = fmaf(c3, v3.z, acc.z); acc.w = fmaf(c3, v3.w, acc.w);
    }
    for (; e < end; e++) {
        int2 p = g_epack[e];
        float4 v = *reinterpret_cast<const float4*>(g_h + (size_t)p.x * HH + c);
        float cf = __int_as_float(p.y);
        acc.x = fmaf(cf, v.x, acc.x); acc.y = fmaf(cf, v.y, acc.y);
        acc.z = fmaf(cf, v.z, acc.z); acc.w = fmaf(cf, v.w, acc.w);
    }

    *reinterpret_cast<float4*>(out + (size_t)n * HH + c) = acc;

    if (doPool) {
        int g = __ldg(&batch[n]);
        red_add_v4(reinterpret_cast<float4*>(g_psum + g * HH + c), acc);
    }
}

// ---------------- z = mean @ lin0_W + lin0_b  -> d_out[pass*G*HO] -------------
__global__ void __launch_bounds__(128)
z_kernel(const float* __restrict__ lin0W, const float* __restrict__ lin0b,
         float* __restrict__ outz)
{
    __shared__ float mean[HH];
    int g = blockIdx.x;
    int t = threadIdx.x;
    float c = fmaxf((float)g_pcnt[g], 1.0f);
    mean[t]       = g_psum[g * HH + t] / c;
    mean[t + 128] = g_psum[g * HH + t + 128] / c;
    __syncthreads();
    float acc = lin0b[t];
#pragma unroll 8
    for (int k = 0; k < HH; k++)
        acc = fmaf(mean[k], __ldg(&lin0W[(size_t)k * HO + t]), acc);
    outz[g * HO + t] = acc;
}

// ---------------- triplet head ------------------------------------------------
__global__ void final_kernel(const float* __restrict__ linW,
                             const float* __restrict__ linb,
                             float* __restrict__ out)
{
    __shared__ int s1, s2;
    int g = threadIdx.x;
    if (g == 0) { s1 = 0; s2 = 0; }
    __syncthreads();

    const float* z0 = out;
    const float* z1 = out + GG * HO;
    const float* z2 = out + 2 * GG * HO;
    const float EPS = 1e-6f;

    float dp = 0.f, dn = 0.f;
    float y1 = linb[0], y2 = linb[0];
#pragma unroll 4
    for (int j = 0; j < HO; j++) {
        float a = z0[g * HO + j];
        float b = z1[g * HO + j];
        float c = z2[g * HO + j];
        float e1 = a - b + EPS; dp = fmaf(e1, e1, dp);
        float e2 = a - c + EPS; dn = fmaf(e2, e2, dn);
        float wa = linW[j], wb = linW[HO + j];
        y1 = fmaf(a, wa, fmaf(b, wb, y1));
        y2 = fmaf(a, wa, fmaf(c, wb, y2));
    }
    dp = sqrtf(dp); dn = sqrtf(dn);
    float sp = 1.0f / (1.0f + expf(-y1));
    float sn = 1.0f / (1.0f + expf(-y2));

    const int base = 3 * GG * HO;
    out[base + 1 + g] = sp;
    out[base + 1 + GG + g] = sn;
    if (dn - dp > 0.f) atomicAdd(&s1, 1);
    if (sp - sn > 0.f) atomicAdd(&s2, 1);
    __syncthreads();
    if (g == 0) {
        out[base] = (float)s1;
        out[base + 1 + 2 * GG] = (float)s2;
    }
}

// ---------------- host orchestration ------------------------------------------
extern "C" void kernel_launch(void* const* d_in, const int* in_sizes, int n_in,
                              void* d_out, int out_size)
{
    const float* x[3]     = { (const float*)d_in[0], (const float*)d_in[1], (const float*)d_in[2] };
    const int*   ei[3]    = { (const int*)d_in[3], (const int*)d_in[4], (const int*)d_in[5] };
    const int*   batch[3] = { (const int*)d_in[6], (const int*)d_in[7], (const int*)d_in[8] };
    const float* W0 = (const float*)d_in[9];
    const float* b0 = (const float*)d_in[10];
    const float* W1 = (const float*)d_in[11];
    const float* b1 = (const float*)d_in[12];
    const float* W2 = (const float*)d_in[13];
    const float* b2 = (const float*)d_in[14];
    const float* lin0W = (const float*)d_in[15];
    const float* lin0b = (const float*)d_in[16];
    const float* linW  = (const float*)d_in[17];
    const float* linb  = (const float*)d_in[18];
    float* out = (float*)d_out;

    float *hptr, *p0ptr, *p1ptr;
    cudaGetSymbolAddress((void**)&hptr,  g_h);
    cudaGetSymbolAddress((void**)&p0ptr, g_p0);
    cudaGetSymbolAddress((void**)&p1ptr, g_p1);

    dim3 gemmGrid((NN + 127) / 128, HH / 128);
    dim3 pullGrid((int)(((long long)NN * 32 + 255) / 256), 2);
    const int NB = (NN + 1023) / 1024;

    for (int p = 0; p < 3; p++) {
        const int* srcp = ei[p];
        const int* dstp = ei[p] + EE;

        // ---- per-pass graph prep ----
        zero_kernel<<<(NN + 255) / 256, 256>>>();
        deg_kernel<<<(EE + 255) / 256, 256>>>(dstp);
        dinv_kernel<<<(NN + 255) / 256, 256>>>();
        scan1_kernel<<<NB, 1024>>>();
        scan2_kernel<<<1, 128>>>();
        scan3_kernel<<<(NN + 255) / 256, 256>>>();
        csr_kernel<<<(EE + 255) / 256, 256>>>(srcp, dstp);
        pcnt_kernel<<<(NN + 255) / 256, 256>>>(batch[p]);

        // ---- layer 0: A = x (K=128) -> h ; pull -> p0
        gemm2_kernel<FIN, false><<<gemmGrid, 256>>>(x[p], W0, hptr);
        pull_kernel<<<pullGrid, 256>>>(b0, p0ptr, nullptr, 0);

        // ---- layer 1: A = relu(p0) (K=256) -> h ; pull -> p1
        gemm2_kernel<HH, true><<<gemmGrid, 256>>>(p0ptr, W1, hptr);
        pull_kernel<<<pullGrid, 256>>>(b1, p1ptr, nullptr, 0);

        // ---- layer 2: A = relu(p1) (K=256) -> h ; pull -> p0, fused pooling
        gemm2_kernel<HH, true><<<gemmGrid, 256>>>(p1ptr, W2, hptr);
        pull_kernel<<<pullGrid, 256>>>(b2, p0ptr, batch[p], 1);

        // ---- z_p = mean @ lin0_W + lin0_b
        z_kernel<<<GG, 128>>>(lin0W, lin0b, out + (size_t)p * GG * HO);
    }

    final_kernel<<<1, GG>>>(linW, linb, out);
}

// round 4
// speedup vs baseline: 2.6413x; 1.0350x over previous
#include <cuda_runtime.h>
#include <cuda_bf16.h>
#include <math.h>

// Problem constants (fixed by the dataset)
#define NN 100000
#define EE 3200000
#define FIN 128
#define HH  256
#define GG  64
#define HO  128   // H/2

typedef unsigned long long u64;

// ---------------- per-pass scratch (static device globals) --------------------
#define NH ((size_t)NN * HH)
__device__ __align__(16) float g_h [3][NH];
__device__ __align__(16) float g_p0[3][NH];
__device__ __align__(16) float g_p1[3][NH];
__device__ float g_dinv [3][NN];
__device__ float g_dinv2[3][NN];
__device__ int   g_deg  [3][NN];
__device__ __align__(16) float g_psum[3][GG * HH];
__device__ int   g_pcnt[3][GG];
__device__ int   g_rowptr[3][NN + 1];
__device__ int   g_off[3][NN];
__device__ int   g_bsum[3][128];
__device__ int   g_bsum2[3][128];
__device__ __align__(8) int2 g_epack[3][EE];   // (src, coef-as-int)

// ---------------- helpers ----------------------------------------------------
__device__ __forceinline__ void red_add_v4(float4* addr, float4 v) {
    asm volatile("red.global.add.v4.f32 [%0], {%1,%2,%3,%4};"
                 :: "l"(addr), "f"(v.x), "f"(v.y), "f"(v.z), "f"(v.w)
                 : "memory");
}
__device__ __forceinline__ u64 dup2(float a) {
    u64 r; asm("mov.b64 %0, {%1, %1};" : "=l"(r) : "f"(a)); return r;
}
__device__ __forceinline__ void fma2(u64& acc, u64 a, u64 b) {
    asm("fma.rn.f32x2 %0, %1, %2, %0;" : "+l"(acc) : "l"(a), "l"(b));
}
__device__ __forceinline__ float2 unp2(u64 v) {
    float2 f; asm("mov.b64 {%0, %1}, %2;" : "=f"(f.x), "=f"(f.y) : "l"(v)); return f;
}

// ---------------- per-pass setup ---------------------------------------------
__global__ void zero_kernel(int p) {
    int i = blockIdx.x * blockDim.x + threadIdx.x;
    if (i < NN)      { g_deg[p][i] = 0; g_off[p][i] = 0; }
    if (i < GG * HH) g_psum[p][i] = 0.f;
    if (i < GG)      g_pcnt[p][i] = 0;
}

__global__ void deg_kernel(const int* __restrict__ dst, int p) {
    int e = blockIdx.x * blockDim.x + threadIdx.x;
    if (e < EE) atomicAdd(&g_deg[p][dst[e]], 1);
}

__global__ void dinv_kernel(int p) {
    int i = blockIdx.x * blockDim.x + threadIdx.x;
    if (i < NN) {
        float d = (float)g_deg[p][i] + 1.0f;
        g_dinv[p][i]  = rsqrtf(d);
        g_dinv2[p][i] = 1.0f / d;
    }
}

// ---------------- exclusive scan of deg -> rowptr ------------------------------
__global__ void scan1_kernel(int p) {
    __shared__ int s[1024];
    int t = threadIdx.x;
    int i = blockIdx.x * 1024 + t;
    int v = (i < NN) ? g_deg[p][i] : 0;
    int x = v;
    s[t] = x;
    __syncthreads();
#pragma unroll
    for (int off = 1; off < 1024; off <<= 1) {
        int y = (t >= off) ? s[t - off] : 0;
        __syncthreads();
        x += y;
        s[t] = x;
        __syncthreads();
    }
    if (i < NN) g_rowptr[p][i] = x - v;
    if (t == 1023) g_bsum[p][blockIdx.x] = x;
}

__global__ void scan2_kernel(int p) {
    __shared__ int s[128];
    int t = threadIdx.x;
    const int NB = (NN + 1023) >> 10;
    int v = (t < NB) ? g_bsum[p][t] : 0;
    int x = v;
    s[t] = x;
    __syncthreads();
#pragma unroll
    for (int off = 1; off < 128; off <<= 1) {
        int y = (t >= off) ? s[t - off] : 0;
        __syncthreads();
        x += y;
        s[t] = x;
        __syncthreads();
    }
    g_bsum2[p][t] = x - v;
}

__global__ void scan3_kernel(int p) {
    int i = blockIdx.x * blockDim.x + threadIdx.x;
    if (i < NN) g_rowptr[p][i] += g_bsum2[p][i >> 10];
    if (i == 0) g_rowptr[p][NN] = EE;
}

// ---------------- CSR build: sort edges by dst, pack (src, coef) ---------------
__global__ void csr_kernel(const int* __restrict__ src, const int* __restrict__ dst, int p) {
    int e = blockIdx.x * blockDim.x + threadIdx.x;
    if (e >= EE) return;
    int s = src[e], d = dst[e];
    float coef = g_dinv[p][s] * g_dinv[p][d];
    int pos = g_rowptr[p][d] + atomicAdd(&g_off[p][d], 1);
    g_epack[p][pos] = make_int2(s, __float_as_int(coef));
}

__global__ void pcnt_kernel(const int* __restrict__ batch, int p) {
    int i = blockIdx.x * blockDim.x + threadIdx.x;
    if (i < NN) atomicAdd(&g_pcnt[p][batch[i]], 1);
}

// ---------------- GEMM: h = act(A) @ W  (FFMA2 128x128 tile) ------------------
template <int K, bool RELU>
__global__ void __launch_bounds__(256, 2)
gemm2_kernel(const float* __restrict__ A, const float* __restrict__ W,
             float* __restrict__ Hout)
{
    __shared__ float As[16][132];
    __shared__ float Bs[16][128];

    const int t  = threadIdx.x;
    const int tx = t & 15;
    const int ty = t >> 4;
    const int rowBase = blockIdx.x * 128;
    const int colBase = blockIdx.y * 128;

    const int arow = t >> 2;
    const int akg  = (t & 3) * 4;
    const int brow = t >> 5;
    const int bcol = (t & 31) * 4;

    const int r0 = rowBase + arow;
    const int r1 = r0 + 64;

    u64 acc[8][4];
#pragma unroll
    for (int i = 0; i < 8; i++)
#pragma unroll
        for (int j = 0; j < 4; j++) acc[i][j] = 0ull;

    float4 pa0, pa1, pb0, pb1;
    {
        pa0 = make_float4(0.f, 0.f, 0.f, 0.f); pa1 = pa0;
        if (r0 < NN) pa0 = *reinterpret_cast<const float4*>(A + (size_t)r0 * K + akg);
        if (r1 < NN) pa1 = *reinterpret_cast<const float4*>(A + (size_t)r1 * K + akg);
        pb0 = *reinterpret_cast<const float4*>(W + (size_t)brow * HH + colBase + bcol);
        pb1 = *reinterpret_cast<const float4*>(W + (size_t)(8 + brow) * HH + colBase + bcol);
    }

    for (int k0 = 0; k0 < K; k0 += 16) {
        float4 a0 = pa0, a1 = pa1, b0 = pb0, b1 = pb1;
        if (RELU) {
            a0.x = fmaxf(a0.x, 0.f); a0.y = fmaxf(a0.y, 0.f);
            a0.z = fmaxf(a0.z, 0.f); a0.w = fmaxf(a0.w, 0.f);
            a1.x = fmaxf(a1.x, 0.f); a1.y = fmaxf(a1.y, 0.f);
            a1.z = fmaxf(a1.z, 0.f); a1.w = fmaxf(a1.w, 0.f);
        }
        As[akg + 0][arow] = a0.x; As[akg + 1][arow] = a0.y;
        As[akg + 2][arow] = a0.z; As[akg + 3][arow] = a0.w;
        As[akg + 0][64 + arow] = a1.x; As[akg + 1][64 + arow] = a1.y;
        As[akg + 2][64 + arow] = a1.z; As[akg + 3][64 + arow] = a1.w;
        *reinterpret_cast<float4*>(&Bs[brow][bcol])     = b0;
        *reinterpret_cast<float4*>(&Bs[brow + 8][bcol]) = b1;
        __syncthreads();

        if (k0 + 16 < K) {
            int kn = k0 + 16;
            pa0 = make_float4(0.f, 0.f, 0.f, 0.f); pa1 = pa0;
            if (r0 < NN) pa0 = *reinterpret_cast<const float4*>(A + (size_t)r0 * K + kn + akg);
            if (r1 < NN) pa1 = *reinterpret_cast<const float4*>(A + (size_t)r1 * K + kn + akg);
            pb0 = *reinterpret_cast<const float4*>(W + (size_t)(kn + brow) * HH + colBase + bcol);
            pb1 = *reinterpret_cast<const float4*>(W + (size_t)(kn + 8 + brow) * HH + colBase + bcol);
        }

#pragma unroll
        for (int kk = 0; kk < 16; kk++) {
            float4 av0 = *reinterpret_cast<const float4*>(&As[kk][ty * 4]);
            float4 av1 = *reinterpret_cast<const float4*>(&As[kk][64 + ty * 4]);
            ulonglong2 bv0 = *reinterpret_cast<const ulonglong2*>(&Bs[kk][tx * 4]);
            ulonglong2 bv1 = *reinterpret_cast<const ulonglong2*>(&Bs[kk][64 + tx * 4]);
            u64 aa;
            aa = dup2(av0.x);
            fma2(acc[0][0], aa, bv0.x); fma2(acc[0][1], aa, bv0.y);
            fma2(acc[0][2], aa, bv1.x); fma2(acc[0][3], aa, bv1.y);
            aa = dup2(av0.y);
            fma2(acc[1][0], aa, bv0.x); fma2(acc[1][1], aa, bv0.y);
            fma2(acc[1][2], aa, bv1.x); fma2(acc[1][3], aa, bv1.y);
            aa = dup2(av0.z);
            fma2(acc[2][0], aa, bv0.x); fma2(acc[2][1], aa, bv0.y);
            fma2(acc[2][2], aa, bv1.x); fma2(acc[2][3], aa, bv1.y);
            aa = dup2(av0.w);
            fma2(acc[3][0], aa, bv0.x); fma2(acc[3][1], aa, bv0.y);
            fma2(acc[3][2], aa, bv1.x); fma2(acc[3][3], aa, bv1.y);
            aa = dup2(av1.x);
            fma2(acc[4][0], aa, bv0.x); fma2(acc[4][1], aa, bv0.y);
            fma2(acc[4][2], aa, bv1.x); fma2(acc[4][3], aa, bv1.y);
            aa = dup2(av1.y);
            fma2(acc[5][0], aa, bv0.x); fma2(acc[5][1], aa, bv0.y);
            fma2(acc[5][2], aa, bv1.x); fma2(acc[5][3], aa, bv1.y);
            aa = dup2(av1.z);
            fma2(acc[6][0], aa, bv0.x); fma2(acc[6][1], aa, bv0.y);
            fma2(acc[6][2], aa, bv1.x); fma2(acc[6][3], aa, bv1.y);
            aa = dup2(av1.w);
            fma2(acc[7][0], aa, bv0.x); fma2(acc[7][1], aa, bv0.y);
            fma2(acc[7][2], aa, bv1.x); fma2(acc[7][3], aa, bv1.y);
        }
        __syncthreads();
    }

#pragma unroll
    for (int i = 0; i < 8; i++) {
        int r = rowBase + ((i < 4) ? (ty * 4 + i) : (64 + ty * 4 + (i - 4)));
        if (r < NN) {
            float2 c0 = unp2(acc[i][0]), c1 = unp2(acc[i][1]);
            float2 c2 = unp2(acc[i][2]), c3 = unp2(acc[i][3]);
            *reinterpret_cast<float4*>(Hout + (size_t)r * HH + colBase + tx * 4)
                = make_float4(c0.x, c0.y, c1.x, c1.y);
            *reinterpret_cast<float4*>(Hout + (size_t)r * HH + colBase + 64 + tx * 4)
                = make_float4(c2.x, c2.y, c3.x, c3.y);
        }
    }
}

// ---------------- pull aggregation --------------------------------------------
__global__ void __launch_bounds__(256)
pull_kernel(const float* __restrict__ bias, float* __restrict__ out,
            const int* __restrict__ batch, int doPool, int p)
{
    int n = (int)((blockIdx.x * (unsigned)blockDim.x + threadIdx.x) >> 5);
    int lane = threadIdx.x & 31;
    if (n >= NN) return;
    int c = blockIdx.y * 128 + lane * 4;

    const float* h = g_h[p];
    float d2 = g_dinv2[p][n];
    float4 b4 = *reinterpret_cast<const float4*>(bias + c);
    float4 hv = *reinterpret_cast<const float4*>(h + (size_t)n * HH + c);
    float4 acc;
    acc.x = fmaf(hv.x, d2, b4.x);
    acc.y = fmaf(hv.y, d2, b4.y);
    acc.z = fmaf(hv.z, d2, b4.z);
    acc.w = fmaf(hv.w, d2, b4.w);

    int beg = g_rowptr[p][n];
    int end = g_rowptr[p][n + 1];
    int e = beg;
    const int2* ep = g_epack[p];

    for (; e + 3 < end; e += 4) {
        int2 p0 = ep[e + 0];
        int2 p1 = ep[e + 1];
        int2 p2 = ep[e + 2];
        int2 p3 = ep[e + 3];
        float4 v0 = *reinterpret_cast<const float4*>(h + (size_t)p0.x * HH + c);
        float4 v1 = *reinterpret_cast<const float4*>(h + (size_t)p1.x * HH + c);
        float4 v2 = *reinterpret_cast<const float4*>(h + (size_t)p2.x * HH + c);
        float4 v3 = *reinterpret_cast<const float4*>(h + (size_t)p3.x * HH + c);
        float c0 = __int_as_float(p0.y), c1 = __int_as_float(p1.y);
        float c2 = __int_as_float(p2.y), c3 = __int_as_float(p3.y);
        acc.x = fmaf(c0, v0.x, acc.x); acc.y = fmaf(c0, v0.y, acc.y);
        acc.z = fmaf(c0, v0.z, acc.z); acc.w = fmaf(c0, v0.w, acc.w);
        acc.x = fmaf(c1, v1.x, acc.x); acc.y = fmaf(c1, v1.y, acc.y);
        acc.z = fmaf(c1, v1.z, acc.z); acc.w = fmaf(c1, v1.w, acc.w);
        acc.x = fmaf(c2, v2.x, acc.x); acc.y = fmaf(c2, v2.y, acc.y);
        acc.z = fmaf(c2, v2.z, acc.z); acc.w = fmaf(c2, v2.w, acc.w);
        acc.x = fmaf(c3, v3.x, acc.x); acc.y = fmaf(c3, v3.y, acc.y);
        acc.z = fmaf(c3, v3.z, acc.z); acc.w = fmaf(c3, v3.w, acc.w);
    }
    for (; e < end; e++) {
        int2 pe = ep[e];
        float4 v = *reinterpret_cast<const float4*>(h + (size_t)pe.x * HH + c);
        float cf = __int_as_float(pe.y);
        acc.x = fmaf(cf, v.x, acc.x); acc.y = fmaf(cf, v.y, acc.y);
        acc.z = fmaf(cf, v.z, acc.z); acc.w = fmaf(cf, v.w, acc.w);
    }

    *reinterpret_cast<float4*>(out + (size_t)n * HH + c) = acc;

    if (doPool) {
        int g = __ldg(&batch[n]);
        red_add_v4(reinterpret_cast<float4*>(g_psum[p] + g * HH + c), acc);
    }
}

// ---------------- z = mean @ lin0_W + lin0_b -----------------------------------
__global__ void __launch_bounds__(128)
z_kernel(const float* __restrict__ lin0W, const float* __restrict__ lin0b,
         float* __restrict__ outz, int p)
{
    __shared__ float mean[HH];
    int g = blockIdx.x;
    int t = threadIdx.x;
    float c = fmaxf((float)g_pcnt[p][g], 1.0f);
    mean[t]       = g_psum[p][g * HH + t] / c;
    mean[t + 128] = g_psum[p][g * HH + t + 128] / c;
    __syncthreads();
    float acc = lin0b[t];
#pragma unroll 8
    for (int k = 0; k < HH; k++)
        acc = fmaf(mean[k], __ldg(&lin0W[(size_t)k * HO + t]), acc);
    outz[g * HO + t] = acc;
}

// ---------------- triplet head ------------------------------------------------
__global__ void final_kernel(const float* __restrict__ linW,
                             const float* __restrict__ linb,
                             float* __restrict__ out)
{
    __shared__ int s1, s2;
    int g = threadIdx.x;
    if (g == 0) { s1 = 0; s2 = 0; }
    __syncthreads();

    const float* z0 = out;
    const float* z1 = out + GG * HO;
    const float* z2 = out + 2 * GG * HO;
    const float EPS = 1e-6f;

    float dp = 0.f, dn = 0.f;
    float y1 = linb[0], y2 = linb[0];
#pragma unroll 4
    for (int j = 0; j < HO; j++) {
        float a = z0[g * HO + j];
        float b = z1[g * HO + j];
        float c = z2[g * HO + j];
        float e1 = a - b + EPS; dp = fmaf(e1, e1, dp);
        float e2 = a - c + EPS; dn = fmaf(e2, e2, dn);
        float wa = linW[j], wb = linW[HO + j];
        y1 = fmaf(a, wa, fmaf(b, wb, y1));
        y2 = fmaf(a, wa, fmaf(c, wb, y2));
    }
    dp = sqrtf(dp); dn = sqrtf(dn);
    float sp = 1.0f / (1.0f + expf(-y1));
    float sn = 1.0f / (1.0f + expf(-y2));

    const int base = 3 * GG * HO;
    out[base + 1 + g] = sp;
    out[base + 1 + GG + g] = sn;
    if (dn - dp > 0.f) atomicAdd(&s1, 1);
    if (sp - sn > 0.f) atomicAdd(&s2, 1);
    __syncthreads();
    if (g == 0) {
        out[base] = (float)s1;
        out[base + 1 + 2 * GG] = (float)s2;
    }
}

// ---------------- host orchestration ------------------------------------------
extern "C" void kernel_launch(void* const* d_in, const int* in_sizes, int n_in,
                              void* d_out, int out_size)
{
    const float* x[3]     = { (const float*)d_in[0], (const float*)d_in[1], (const float*)d_in[2] };
    const int*   ei[3]    = { (const int*)d_in[3], (const int*)d_in[4], (const int*)d_in[5] };
    const int*   batch[3] = { (const int*)d_in[6], (const int*)d_in[7], (const int*)d_in[8] };
    const float* W0 = (const float*)d_in[9];
    const float* b0 = (const float*)d_in[10];
    const float* W1 = (const float*)d_in[11];
    const float* b1 = (const float*)d_in[12];
    const float* W2 = (const float*)d_in[13];
    const float* b2 = (const float*)d_in[14];
    const float* lin0W = (const float*)d_in[15];
    const float* lin0b = (const float*)d_in[16];
    const float* linW  = (const float*)d_in[17];
    const float* linb  = (const float*)d_in[18];
    float* out = (float*)d_out;

    // one-time infra (host-side; the captured work graph is identical every call)
    static cudaStream_t st[3];
    static cudaEvent_t evRoot, evDone[3];
    static bool inited = false;
    if (!inited) {
        for (int i = 0; i < 3; i++) cudaStreamCreateWithFlags(&st[i], cudaStreamNonBlocking);
        cudaEventCreateWithFlags(&evRoot, cudaEventDisableTiming);
        for (int i = 0; i < 3; i++) cudaEventCreateWithFlags(&evDone[i], cudaEventDisableTiming);
        inited = true;
    }

    float *hptr[3], *p0ptr[3], *p1ptr[3];
    {
        float* base;
        cudaGetSymbolAddress((void**)&base, g_h);
        for (int i = 0; i < 3; i++) hptr[i] = base + (size_t)i * NH;
        cudaGetSymbolAddress((void**)&base, g_p0);
        for (int i = 0; i < 3; i++) p0ptr[i] = base + (size_t)i * NH;
        cudaGetSymbolAddress((void**)&base, g_p1);
        for (int i = 0; i < 3; i++) p1ptr[i] = base + (size_t)i * NH;
    }

    dim3 gemmGrid((NN + 127) / 128, HH / 128);
    dim3 pullGrid((int)(((long long)NN * 32 + 255) / 256), 2);
    const int NB = (NN + 1023) / 1024;

    // fork: all passes branch off the (captured) legacy stream
    cudaEventRecord(evRoot, 0);

    for (int p = 0; p < 3; p++) {
        cudaStream_t s = st[p];
        cudaStreamWaitEvent(s, evRoot, 0);

        const int* srcp = ei[p];
        const int* dstp = ei[p] + EE;

        // ---- per-pass graph prep ----
        zero_kernel<<<(NN + 255) / 256, 256, 0, s>>>(p);
        deg_kernel<<<(EE + 255) / 256, 256, 0, s>>>(dstp, p);
        dinv_kernel<<<(NN + 255) / 256, 256, 0, s>>>(p);
        scan1_kernel<<<NB, 1024, 0, s>>>(p);
        scan2_kernel<<<1, 128, 0, s>>>(p);
        scan3_kernel<<<(NN + 255) / 256, 256, 0, s>>>(p);
        csr_kernel<<<(EE + 255) / 256, 256, 0, s>>>(srcp, dstp, p);
        pcnt_kernel<<<(NN + 255) / 256, 256, 0, s>>>(batch[p], p);

        // ---- layer 0: A = x (K=128) -> h ; pull -> p0
        gemm2_kernel<FIN, false><<<gemmGrid, 256, 0, s>>>(x[p], W0, hptr[p]);
        pull_kernel<<<pullGrid, 256, 0, s>>>(b0, p0ptr[p], nullptr, 0, p);

        // ---- layer 1: A = relu(p0) (K=256) -> h ; pull -> p1
        gemm2_kernel<HH, true><<<gemmGrid, 256, 0, s>>>(p0ptr[p], W1, hptr[p]);
        pull_kernel<<<pullGrid, 256, 0, s>>>(b1, p1ptr[p], nullptr, 0, p);

        // ---- layer 2: A = relu(p1) (K=256) -> h ; pull -> p0 + pooling
        gemm2_kernel<HH, true><<<gemmGrid, 256, 0, s>>>(p1ptr[p], W2, hptr[p]);
        pull_kernel<<<pullGrid, 256, 0, s>>>(b2, p0ptr[p], batch[p], 1, p);

        // ---- z_p = mean @ lin0_W + lin0_b
        z_kernel<<<GG, 128, 0, s>>>(lin0W, lin0b, out + (size_t)p * GG * HO, p);

        cudaEventRecord(evDone[p], s);
    }

    // join back onto the legacy stream
    for (int p = 0; p < 3; p++) cudaStreamWaitEvent(0, evDone[p], 0);

    final_kernel<<<1, GG>>>(linW, linb, out);
}

// round 7
// speedup vs baseline: 2.8889x; 1.0938x over previous
#include <cuda_runtime.h>
#include <cuda_bf16.h>
#include <stdint.h>
#include <math.h>

// Problem constants (fixed by the dataset)
#define NN 100000
#define EE 3200000
#define FIN 128
#define HH  256
#define GG  64
#define HO  128   // H/2

typedef unsigned long long u64;

// ---------------- per-pass scratch (static device globals) --------------------
#define NH ((size_t)NN * HH)
__device__ __align__(16) float g_h [3][NH];
__device__ __align__(16) float g_p0[3][NH];
__device__ __align__(16) float g_p1[3][NH];
__device__ float g_dinv [3][NN];
__device__ float g_dinv2[3][NN];
__device__ int   g_deg  [3][NN];
__device__ __align__(16) float g_psum[3][GG * HH];
__device__ int   g_pcnt[3][GG];
__device__ int   g_rowptr[3][NN + 1];
__device__ int   g_off[3][NN];
__device__ int   g_bsum[3][128];
__device__ int   g_bsum2[3][128];
__device__ __align__(8) int2 g_epack[3][EE];   // (src, coef-as-int)

// ---------------- helpers ----------------------------------------------------
__device__ __forceinline__ void red_add_v4(float4* addr, float4 v) {
    asm volatile("red.global.add.v4.f32 [%0], {%1,%2,%3,%4};"
                 :: "l"(addr), "f"(v.x), "f"(v.y), "f"(v.z), "f"(v.w)
                 : "memory");
}
__device__ __forceinline__ u64 dup2(float a) {
    u64 r; asm("mov.b64 %0, {%1, %1};" : "=l"(r) : "f"(a)); return r;
}
__device__ __forceinline__ void fma2(u64& acc, u64 a, u64 b) {
    asm("fma.rn.f32x2 %0, %1, %2, %0;" : "+l"(acc) : "l"(a), "l"(b));
}
__device__ __forceinline__ float2 unp2(u64 v) {
    float2 f; asm("mov.b64 {%0, %1}, %2;" : "=f"(f.x), "=f"(f.y) : "l"(v)); return f;
}

// ---------------- per-pass setup ---------------------------------------------
__global__ void zero_kernel(int p) {
    int i = blockIdx.x * blockDim.x + threadIdx.x;
    if (i < NN)      { g_deg[p][i] = 0; g_off[p][i] = 0; }
    if (i < GG * HH) g_psum[p][i] = 0.f;
    if (i < GG)      g_pcnt[p][i] = 0;
}

__global__ void deg_kernel(const int* __restrict__ dst, int p) {
    int e = blockIdx.x * blockDim.x + threadIdx.x;
    if (e < EE) atomicAdd(&g_deg[p][dst[e]], 1);
}

__global__ void dinv_kernel(int p) {
    int i = blockIdx.x * blockDim.x + threadIdx.x;
    if (i < NN) {
        float d = (float)g_deg[p][i] + 1.0f;
        g_dinv[p][i]  = rsqrtf(d);
        g_dinv2[p][i] = 1.0f / d;
    }
}

// ---------------- exclusive scan of deg -> rowptr ------------------------------
__global__ void scan1_kernel(int p) {
    __shared__ int s[1024];
    int t = threadIdx.x;
    int i = blockIdx.x * 1024 + t;
    int v = (i < NN) ? g_deg[p][i] : 0;
    int x = v;
    s[t] = x;
    __syncthreads();
#pragma unroll
    for (int off = 1; off < 1024; off <<= 1) {
        int y = (t >= off) ? s[t - off] : 0;
        __syncthreads();
        x += y;
        s[t] = x;
        __syncthreads();
    }
    if (i < NN) g_rowptr[p][i] = x - v;
    if (t == 1023) g_bsum[p][blockIdx.x] = x;
}

__global__ void scan2_kernel(int p) {
    __shared__ int s[128];
    int t = threadIdx.x;
    const int NB = (NN + 1023) >> 10;
    int v = (t < NB) ? g_bsum[p][t] : 0;
    int x = v;
    s[t] = x;
    __syncthreads();
#pragma unroll
    for (int off = 1; off < 128; off <<= 1) {
        int y = (t >= off) ? s[t - off] : 0;
        __syncthreads();
        x += y;
        s[t] = x;
        __syncthreads();
    }
    g_bsum2[p][t] = x - v;
}

__global__ void scan3_kernel(int p) {
    int i = blockIdx.x * blockDim.x + threadIdx.x;
    if (i < NN) g_rowptr[p][i] += g_bsum2[p][i >> 10];
    if (i == 0) g_rowptr[p][NN] = EE;
}

__global__ void csr_kernel(const int* __restrict__ src, const int* __restrict__ dst, int p) {
    int e = blockIdx.x * blockDim.x + threadIdx.x;
    if (e >= EE) return;
    int s = src[e], d = dst[e];
    float coef = g_dinv[p][s] * g_dinv[p][d];
    int pos = g_rowptr[p][d] + atomicAdd(&g_off[p][d], 1);
    g_epack[p][pos] = make_int2(s, __float_as_int(coef));
}

__global__ void pcnt_kernel(const int* __restrict__ batch, int p) {
    int i = blockIdx.x * blockDim.x + threadIdx.x;
    if (i < NN) atomicAdd(&g_pcnt[p][batch[i]], 1);
}

// ---------------- layer-0 input aggregation: aggx = Â x  (128 cols) ------------
// One warp per node; 32 lanes x float4 = 128 cols in one shot.
__global__ void __launch_bounds__(256)
pullx_kernel(const float* __restrict__ x, float* __restrict__ aggx, int p)
{
    int n = (int)((blockIdx.x * (unsigned)blockDim.x + threadIdx.x) >> 5);
    int lane = threadIdx.x & 31;
    if (n >= NN) return;
    int c = lane * 4;

    float d2 = g_dinv2[p][n];
    float4 acc = *reinterpret_cast<const float4*>(x + (size_t)n * FIN + c);
    acc.x *= d2; acc.y *= d2; acc.z *= d2; acc.w *= d2;

    int e = g_rowptr[p][n];
    int end = g_rowptr[p][n + 1];
    const int2* ep = g_epack[p];

    for (; e + 3 < end; e += 4) {
        int2 p0 = ep[e + 0];
        int2 p1 = ep[e + 1];
        int2 p2 = ep[e + 2];
        int2 p3 = ep[e + 3];
        float4 v0 = *reinterpret_cast<const float4*>(x + (size_t)p0.x * FIN + c);
        float4 v1 = *reinterpret_cast<const float4*>(x + (size_t)p1.x * FIN + c);
        float4 v2 = *reinterpret_cast<const float4*>(x + (size_t)p2.x * FIN + c);
        float4 v3 = *reinterpret_cast<const float4*>(x + (size_t)p3.x * FIN + c);
        float c0 = __int_as_float(p0.y), c1 = __int_as_float(p1.y);
        float c2 = __int_as_float(p2.y), c3 = __int_as_float(p3.y);
        acc.x = fmaf(c0, v0.x, acc.x); acc.y = fmaf(c0, v0.y, acc.y);
        acc.z = fmaf(c0, v0.z, acc.z); acc.w = fmaf(c0, v0.w, acc.w);
        acc.x = fmaf(c1, v1.x, acc.x); acc.y = fmaf(c1, v1.y, acc.y);
        acc.z = fmaf(c1, v1.z, acc.z); acc.w = fmaf(c1, v1.w, acc.w);
        acc.x = fmaf(c2, v2.x, acc.x); acc.y = fmaf(c2, v2.y, acc.y);
        acc.z = fmaf(c2, v2.z, acc.z); acc.w = fmaf(c2, v2.w, acc.w);
        acc.x = fmaf(c3, v3.x, acc.x); acc.y = fmaf(c3, v3.y, acc.y);
        acc.z = fmaf(c3, v3.z, acc.z); acc.w = fmaf(c3, v3.w, acc.w);
    }
    for (; e < end; e++) {
        int2 pe = ep[e];
        float4 v = *reinterpret_cast<const float4*>(x + (size_t)pe.x * FIN + c);
        float cf = __int_as_float(pe.y);
        acc.x = fmaf(cf, v.x, acc.x); acc.y = fmaf(cf, v.y, acc.y);
        acc.z = fmaf(cf, v.z, acc.z); acc.w = fmaf(cf, v.w, acc.w);
    }

    *reinterpret_cast<float4*>(aggx + (size_t)n * FIN + c) = acc;
}

// ---------------- GEMM: out = act(A) @ W (+ bias)  (FFMA2 128x128 tile) -------
template <int K, bool RELU, bool BIAS>
__global__ void __launch_bounds__(256, 2)
gemm2_kernel(const float* __restrict__ A, const float* __restrict__ W,
             const float* __restrict__ bias, float* __restrict__ Hout)
{
    __shared__ float As[16][132];
    __shared__ float Bs[16][128];

    const int t  = threadIdx.x;
    const int tx = t & 15;
    const int ty = t >> 4;
    const int rowBase = blockIdx.x * 128;
    const int colBase = blockIdx.y * 128;

    const int arow = t >> 2;
    const int akg  = (t & 3) * 4;
    const int brow = t >> 5;
    const int bcol = (t & 31) * 4;

    const int r0 = rowBase + arow;
    const int r1 = r0 + 64;

    u64 acc[8][4];
#pragma unroll
    for (int i = 0; i < 8; i++)
#pragma unroll
        for (int j = 0; j < 4; j++) acc[i][j] = 0ull;

    float4 pa0, pa1, pb0, pb1;
    {
        pa0 = make_float4(0.f, 0.f, 0.f, 0.f); pa1 = pa0;
        if (r0 < NN) pa0 = *reinterpret_cast<const float4*>(A + (size_t)r0 * K + akg);
        if (r1 < NN) pa1 = *reinterpret_cast<const float4*>(A + (size_t)r1 * K + akg);
        pb0 = *reinterpret_cast<const float4*>(W + (size_t)brow * HH + colBase + bcol);
        pb1 = *reinterpret_cast<const float4*>(W + (size_t)(8 + brow) * HH + colBase + bcol);
    }

    for (int k0 = 0; k0 < K; k0 += 16) {
        float4 a0 = pa0, a1 = pa1, b0 = pb0, b1 = pb1;
        if (RELU) {
            a0.x = fmaxf(a0.x, 0.f); a0.y = fmaxf(a0.y, 0.f);
            a0.z = fmaxf(a0.z, 0.f); a0.w = fmaxf(a0.w, 0.f);
            a1.x = fmaxf(a1.x, 0.f); a1.y = fmaxf(a1.y, 0.f);
            a1.z = fmaxf(a1.z, 0.f); a1.w = fmaxf(a1.w, 0.f);
        }
        As[akg + 0][arow] = a0.x; As[akg + 1][arow] = a0.y;
        As[akg + 2][arow] = a0.z; As[akg + 3][arow] = a0.w;
        As[akg + 0][64 + arow] = a1.x; As[akg + 1][64 + arow] = a1.y;
        As[akg + 2][64 + arow] = a1.z; As[akg + 3][64 + arow] = a1.w;
        *reinterpret_cast<float4*>(&Bs[brow][bcol])     = b0;
        *reinterpret_cast<float4*>(&Bs[brow + 8][bcol]) = b1;
        __syncthreads();

        if (k0 + 16 < K) {
            int kn = k0 + 16;
            pa0 = make_float4(0.f, 0.f, 0.f, 0.f); pa1 = pa0;
            if (r0 < NN) pa0 = *reinterpret_cast<const float4*>(A + (size_t)r0 * K + kn + akg);
            if (r1 < NN) pa1 = *reinterpret_cast<const float4*>(A + (size_t)r1 * K + kn + akg);
            pb0 = *reinterpret_cast<const float4*>(W + (size_t)(kn + brow) * HH + colBase + bcol);
            pb1 = *reinterpret_cast<const float4*>(W + (size_t)(kn + 8 + brow) * HH + colBase + bcol);
        }

#pragma unroll
        for (int kk = 0; kk < 16; kk++) {
            float4 av0 = *reinterpret_cast<const float4*>(&As[kk][ty * 4]);
            float4 av1 = *reinterpret_cast<const float4*>(&As[kk][64 + ty * 4]);
            ulonglong2 bv0 = *reinterpret_cast<const ulonglong2*>(&Bs[kk][tx * 4]);
            ulonglong2 bv1 = *reinterpret_cast<const ulonglong2*>(&Bs[kk][64 + tx * 4]);
            u64 aa;
            aa = dup2(av0.x);
            fma2(acc[0][0], aa, bv0.x); fma2(acc[0][1], aa, bv0.y);
            fma2(acc[0][2], aa, bv1.x); fma2(acc[0][3], aa, bv1.y);
            aa = dup2(av0.y);
            fma2(acc[1][0], aa, bv0.x); fma2(acc[1][1], aa, bv0.y);
            fma2(acc[1][2], aa, bv1.x); fma2(acc[1][3], aa, bv1.y);
            aa = dup2(av0.z);
            fma2(acc[2][0], aa, bv0.x); fma2(acc[2][1], aa, bv0.y);
            fma2(acc[2][2], aa, bv1.x); fma2(acc[2][3], aa, bv1.y);
            aa = dup2(av0.w);
            fma2(acc[3][0], aa, bv0.x); fma2(acc[3][1], aa, bv0.y);
            fma2(acc[3][2], aa, bv1.x); fma2(acc[3][3], aa, bv1.y);
            aa = dup2(av1.x);
            fma2(acc[4][0], aa, bv0.x); fma2(acc[4][1], aa, bv0.y);
            fma2(acc[4][2], aa, bv1.x); fma2(acc[4][3], aa, bv1.y);
            aa = dup2(av1.y);
            fma2(acc[5][0], aa, bv0.x); fma2(acc[5][1], aa, bv0.y);
            fma2(acc[5][2], aa, bv1.x); fma2(acc[5][3], aa, bv1.y);
            aa = dup2(av1.z);
            fma2(acc[6][0], aa, bv0.x); fma2(acc[6][1], aa, bv0.y);
            fma2(acc[6][2], aa, bv1.x); fma2(acc[6][3], aa, bv1.y);
            aa = dup2(av1.w);
            fma2(acc[7][0], aa, bv0.x); fma2(acc[7][1], aa, bv0.y);
            fma2(acc[7][2], aa, bv1.x); fma2(acc[7][3], aa, bv1.y);
        }
        __syncthreads();
    }

    float4 bias0 = make_float4(0.f, 0.f, 0.f, 0.f), bias1 = bias0;
    if (BIAS) {
        bias0 = *reinterpret_cast<const float4*>(bias + colBase + tx * 4);
        bias1 = *reinterpret_cast<const float4*>(bias + colBase + 64 + tx * 4);
    }
#pragma unroll
    for (int i = 0; i < 8; i++) {
        int r = rowBase + ((i < 4) ? (ty * 4 + i) : (64 + ty * 4 + (i - 4)));
        if (r < NN) {
            float2 c0 = unp2(acc[i][0]), c1 = unp2(acc[i][1]);
            float2 c2 = unp2(acc[i][2]), c3 = unp2(acc[i][3]);
            float4 o0 = make_float4(c0.x, c0.y, c1.x, c1.y);
            float4 o1 = make_float4(c2.x, c2.y, c3.x, c3.y);
            if (BIAS) {
                o0.x += bias0.x; o0.y += bias0.y; o0.z += bias0.z; o0.w += bias0.w;
                o1.x += bias1.x; o1.y += bias1.y; o1.z += bias1.z; o1.w += bias1.w;
            }
            *reinterpret_cast<float4*>(Hout + (size_t)r * HH + colBase + tx * 4) = o0;
            *reinterpret_cast<float4*>(Hout + (size_t)r * HH + colBase + 64 + tx * 4) = o1;
        }
    }
}

// ---------------- pull aggregation (layers 1,2) --------------------------------
__global__ void __launch_bounds__(256)
pull_kernel(const float* __restrict__ bias, float* __restrict__ out,
            const int* __restrict__ batch, int doPool, int p)
{
    int n = (int)((blockIdx.x * (unsigned)blockDim.x + threadIdx.x) >> 5);
    int lane = threadIdx.x & 31;
    if (n >= NN) return;
    int c = blockIdx.y * 128 + lane * 4;

    const float* h = g_h[p];
    float d2 = g_dinv2[p][n];
    float4 b4 = *reinterpret_cast<const float4*>(bias + c);
    float4 hv = *reinterpret_cast<const float4*>(h + (size_t)n * HH + c);
    float4 acc;
    acc.x = fmaf(hv.x, d2, b4.x);
    acc.y = fmaf(hv.y, d2, b4.y);
    acc.z = fmaf(hv.z, d2, b4.z);
    acc.w = fmaf(hv.w, d2, b4.w);

    int beg = g_rowptr[p][n];
    int end = g_rowptr[p][n + 1];
    int e = beg;
    const int2* ep = g_epack[p];

    for (; e + 3 < end; e += 4) {
        int2 p0 = ep[e + 0];
        int2 p1 = ep[e + 1];
        int2 p2 = ep[e + 2];
        int2 p3 = ep[e + 3];
        float4 v0 = *reinterpret_cast<const float4*>(h + (size_t)p0.x * HH + c);
        float4 v1 = *reinterpret_cast<const float4*>(h + (size_t)p1.x * HH + c);
        float4 v2 = *reinterpret_cast<const float4*>(h + (size_t)p2.x * HH + c);
        float4 v3 = *reinterpret_cast<const float4*>(h + (size_t)p3.x * HH + c);
        float c0 = __int_as_float(p0.y), c1 = __int_as_float(p1.y);
        float c2 = __int_as_float(p2.y), c3 = __int_as_float(p3.y);
        acc.x = fmaf(c0, v0.x, acc.x); acc.y = fmaf(c0, v0.y, acc.y);
        acc.z = fmaf(c0, v0.z, acc.z); acc.w = fmaf(c0, v0.w, acc.w);
        acc.x = fmaf(c1, v1.x, acc.x); acc.y = fmaf(c1, v1.y, acc.y);
        acc.z = fmaf(c1, v1.z, acc.z); acc.w = fmaf(c1, v1.w, acc.w);
        acc.x = fmaf(c2, v2.x, acc.x); acc.y = fmaf(c2, v2.y, acc.y);
        acc.z = fmaf(c2, v2.z, acc.z); acc.w = fmaf(c2, v2.w, acc.w);
        acc.x = fmaf(c3, v3.x, acc.x); acc.y = fmaf(c3, v3.y, acc.y);
        acc.z = fmaf(c3, v3.z, acc.z); acc.w = fmaf(c3, v3.w, acc.w);
    }
    for (; e < end; e++) {
        int2 pe = ep[e];
        float4 v = *reinterpret_cast<const float4*>(h + (size_t)pe.x * HH + c);
        float cf = __int_as_float(pe.y);
        acc.x = fmaf(cf, v.x, acc.x); acc.y = fmaf(cf, v.y, acc.y);
        acc.z = fmaf(cf, v.z, acc.z); acc.w = fmaf(cf, v.w, acc.w);
    }

    *reinterpret_cast<float4*>(out + (size_t)n * HH + c) = acc;

    if (doPool) {
        int g = __ldg(&batch[n]);
        red_add_v4(reinterpret_cast<float4*>(g_psum[p] + g * HH + c), acc);
    }
}

// ---------------- z = mean @ lin0_W + lin0_b -----------------------------------
__global__ void __launch_bounds__(128)
z_kernel(const float* __restrict__ lin0W, const float* __restrict__ lin0b,
         float* __restrict__ outz, int p)
{
    __shared__ float mean[HH];
    int g = blockIdx.x;
    int t = threadIdx.x;
    float c = fmaxf((float)g_pcnt[p][g], 1.0f);
    mean[t]       = g_psum[p][g * HH + t] / c;
    mean[t + 128] = g_psum[p][g * HH + t + 128] / c;
    __syncthreads();
    float acc = lin0b[t];
#pragma unroll 8
    for (int k = 0; k < HH; k++)
        acc = fmaf(mean[k], __ldg(&lin0W[(size_t)k * HO + t]), acc);
    outz[g * HO + t] = acc;
}

// ---------------- triplet head ------------------------------------------------
__global__ void final_kernel(const float* __restrict__ linW,
                             const float* __restrict__ linb,
                             float* __restrict__ out)
{
    __shared__ int s1, s2;
    int g = threadIdx.x;
    if (g == 0) { s1 = 0; s2 = 0; }
    __syncthreads();

    const float* z0 = out;
    const float* z1 = out + GG * HO;
    const float* z2 = out + 2 * GG * HO;
    const float EPS = 1e-6f;

    float dp = 0.f, dn = 0.f;
    float y1 = linb[0], y2 = linb[0];
#pragma unroll 4
    for (int j = 0; j < HO; j++) {
        float a = z0[g * HO + j];
        float b = z1[g * HO + j];
        float c = z2[g * HO + j];
        float e1 = a - b + EPS; dp = fmaf(e1, e1, dp);
        float e2 = a - c + EPS; dn = fmaf(e2, e2, dn);
        float wa = linW[j], wb = linW[HO + j];
        y1 = fmaf(a, wa, fmaf(b, wb, y1));
        y2 = fmaf(a, wa, fmaf(c, wb, y2));
    }
    dp = sqrtf(dp); dn = sqrtf(dn);
    float sp = 1.0f / (1.0f + expf(-y1));
    float sn = 1.0f / (1.0f + expf(-y2));

    const int base = 3 * GG * HO;
    out[base + 1 + g] = sp;
    out[base + 1 + GG + g] = sn;
    if (dn - dp > 0.f) atomicAdd(&s1, 1);
    if (sp - sn > 0.f) atomicAdd(&s2, 1);
    __syncthreads();
    if (g == 0) {
        out[base] = (float)s1;
        out[base + 1 + 2 * GG] = (float)s2;
    }
}

// ---------------- host orchestration ------------------------------------------
extern "C" void kernel_launch(void* const* d_in, const int* in_sizes, int n_in,
                              void* d_out, int out_size)
{
    const float* x[3]     = { (const float*)d_in[0], (const float*)d_in[1], (const float*)d_in[2] };
    const int*   ei[3]    = { (const int*)d_in[3], (const int*)d_in[4], (const int*)d_in[5] };
    const int*   batch[3] = { (const int*)d_in[6], (const int*)d_in[7], (const int*)d_in[8] };
    const float* W0 = (const float*)d_in[9];
    const float* b0 = (const float*)d_in[10];
    const float* W1 = (const float*)d_in[11];
    const float* b1 = (const float*)d_in[12];
    const float* W2 = (const float*)d_in[13];
    const float* b2 = (const float*)d_in[14];
    const float* lin0W = (const float*)d_in[15];
    const float* lin0b = (const float*)d_in[16];
    const float* linW  = (const float*)d_in[17];
    const float* linb  = (const float*)d_in[18];
    float* out = (float*)d_out;

    static cudaStream_t st[3];
    static cudaEvent_t evRoot, evDone[3];
    static bool inited = false;
    if (!inited) {
        for (int i = 0; i < 3; i++) cudaStreamCreateWithFlags(&st[i], cudaStreamNonBlocking);
        cudaEventCreateWithFlags(&evRoot, cudaEventDisableTiming);
        for (int i = 0; i < 3; i++) cudaEventCreateWithFlags(&evDone[i], cudaEventDisableTiming);
        inited = true;
    }

    float *hptr[3], *p0ptr[3], *p1ptr[3];
    {
        float* base;
        cudaGetSymbolAddress((void**)&base, g_h);
        for (int i = 0; i < 3; i++) hptr[i] = base + (size_t)i * NH;
        cudaGetSymbolAddress((void**)&base, g_p0);
        for (int i = 0; i < 3; i++) p0ptr[i] = base + (size_t)i * NH;
        cudaGetSymbolAddress((void**)&base, g_p1);
        for (int i = 0; i < 3; i++) p1ptr[i] = base + (size_t)i * NH;
    }

    dim3 gemmGrid((NN + 127) / 128, HH / 128);
    dim3 pullGrid((int)(((long long)NN * 32 + 255) / 256), 2);
    int  pullxBlocks = (int)(((long long)NN * 32 + 255) / 256);
    const int NB = (NN + 1023) / 1024;

    cudaEventRecord(evRoot, 0);

    for (int p = 0; p < 3; p++) {
        cudaStream_t s = st[p];
        cudaStreamWaitEvent(s, evRoot, 0);

        const int* srcp = ei[p];
        const int* dstp = ei[p] + EE;

        // ---- per-pass graph prep ----
        zero_kernel<<<(NN + 255) / 256, 256, 0, s>>>(p);
        deg_kernel<<<(EE + 255) / 256, 256, 0, s>>>(dstp, p);
        dinv_kernel<<<(NN + 255) / 256, 256, 0, s>>>(p);
        scan1_kernel<<<NB, 1024, 0, s>>>(p);
        scan2_kernel<<<1, 128, 0, s>>>(p);
        scan3_kernel<<<(NN + 255) / 256, 256, 0, s>>>(p);
        csr_kernel<<<(EE + 255) / 256, 256, 0, s>>>(srcp, dstp, p);
        pcnt_kernel<<<(NN + 255) / 256, 256, 0, s>>>(batch[p], p);

        // ---- layer 0 (aggregate-first): aggx = Â x (128 cols, into p1 scratch)
        //      then p0 = aggx @ W0 + b0   (no relu on A, bias in epilogue)
        pullx_kernel<<<pullxBlocks, 256, 0, s>>>(x[p], p1ptr[p], p);
        gemm2_kernel<FIN, false, true><<<gemmGrid, 256, 0, s>>>(p1ptr[p], W0, b0, p0ptr[p]);

        // ---- layer 1: h = relu(p0) @ W1 ; pull+b1 -> p1
        gemm2_kernel<HH, true, false><<<gemmGrid, 256, 0, s>>>(p0ptr[p], W1, nullptr, hptr[p]);
        pull_kernel<<<pullGrid, 256, 0, s>>>(b1, p1ptr[p], nullptr, 0, p);

        // ---- layer 2: h = relu(p1) @ W2 ; pull+b2 -> p0 + pooling
        gemm2_kernel<HH, true, false><<<gemmGrid, 256, 0, s>>>(p1ptr[p], W2, nullptr, hptr[p]);
        pull_kernel<<<pullGrid, 256, 0, s>>>(b2, p0ptr[p], batch[p], 1, p);

        // ---- z_p = mean @ lin0_W + lin0_b
        z_kernel<<<GG, 128, 0, s>>>(lin0W, lin0b, out + (size_t)p * GG * HO, p);

        cudaEventRecord(evDone[p], s);
    }

    for (int p = 0; p < 3; p++) cudaStreamWaitEvent(0, evDone[p], 0);

    final_kernel<<<1, GG>>>(linW, linb, out);
}